// round 4
// baseline (speedup 1.0000x reference)
#include <cuda_runtime.h>
#include <cstdint>
#include <math.h>

#define NB 16
#define NC 256

// ---------------- scratch (device globals: no allocs allowed) ----------------
__device__ float g_D1[NB*NC*4096];
__device__ float g_D2[NB*NC*2048];
__device__ float g_D3[NB*NC*1024];
__device__ float g_A3[NB*NC*1024];
__device__ float g_S [NB*NC*8192];
__device__ float g_Wr[4*NC*NC];     // tf32-rounded weights: ab_w1, ab_w2, db_w1, db_w2

// ---------------- db4 filters ----------------
__constant__ float c_dec_lo[8] = {-0.010597401785069032f, 0.0328830116668852f, 0.030841381835560764f, -0.18703481171888114f, -0.027983769416859854f, 0.6308807679298589f, 0.7148465705529157f, 0.2303778133088965f};
__constant__ float c_dec_hi[8] = {-0.2303778133088965f, 0.7148465705529157f, -0.6308807679298589f, -0.027983769416859854f, 0.18703481171888114f, 0.030841381835560764f, -0.0328830116668852f, -0.010597401785069032f};
__constant__ float c_rec_lo[8] = {0.2303778133088965f, 0.7148465705529157f, 0.6308807679298589f, -0.027983769416859854f, -0.18703481171888114f, 0.030841381835560764f, 0.0328830116668852f, -0.010597401785069032f};
__constant__ float c_rec_hi[8] = {-0.010597401785069032f, -0.0328830116668852f, 0.030841381835560764f, 0.18703481171888114f, -0.027983769416859854f, -0.6308807679298589f, 0.7148465705529157f, -0.2303778133088965f};

// ================= helpers =================
__device__ __forceinline__ uint32_t smem_u32(const void* p) {
    uint32_t a;
    asm("{ .reg .u64 t; cvta.to.shared.u64 t, %1; cvt.u32.u64 %0, t; }" : "=r"(a) : "l"(p));
    return a;
}
__device__ __forceinline__ void cp16(uint32_t dst, const void* src) {
    asm volatile("cp.async.cg.shared.global [%0], [%1], 16;" :: "r"(dst), "l"(src));
}
__device__ __forceinline__ void cp_commit() { asm volatile("cp.async.commit_group;" ::: "memory"); }
__device__ __forceinline__ void cp_wait1()  { asm volatile("cp.async.wait_group 1;" ::: "memory"); }

__device__ __forceinline__ void mma_tf32(float* c, const uint32_t* a, const uint32_t* b) {
    asm volatile("mma.sync.aligned.m16n8k8.row.col.f32.tf32.tf32.f32 "
                 "{%0,%1,%2,%3}, {%4,%5,%6,%7}, {%8,%9}, {%0,%1,%2,%3};"
                 : "+f"(c[0]), "+f"(c[1]), "+f"(c[2]), "+f"(c[3])
                 : "r"(a[0]), "r"(a[1]), "r"(a[2]), "r"(a[3]), "r"(b[0]), "r"(b[1]));
}
__device__ __forceinline__ uint32_t to_tf32(float f) {
    uint32_t r;
    asm("cvt.rna.tf32.f32 %0, %1;" : "=r"(r) : "f"(f));
    return r;
}
__device__ __forceinline__ float gelu_tanh(float x) {
    const float k0 = 0.7978845608028654f;
    const float k1 = 0.044715f;
    float x3 = x * x * x;
    float t = tanhf(k0 * (x + k1 * x3));
    return 0.5f * x * (1.f + t);
}

// ---------------- round weights to tf32 ----------------
__global__ __launch_bounds__(256) void roundw_kernel(const float* __restrict__ w0,
                                                     const float* __restrict__ w1,
                                                     const float* __restrict__ w2,
                                                     const float* __restrict__ w3,
                                                     float* __restrict__ out) {
    int i = blockIdx.x * 256 + threadIdx.x;
    const float* src[4] = {w0, w1, w2, w3};
    for (int m = 0; m < 4; m++) {
        float4 v = *(const float4*)(src[m] + i * 4);
        float4 o = make_float4(__uint_as_float(to_tf32(v.x)), __uint_as_float(to_tf32(v.y)),
                               __uint_as_float(to_tf32(v.z)), __uint_as_float(to_tf32(v.w)));
        *(float4*)(out + m * NC * NC + i * 4) = o;
    }
}

// ================= fused 3-level DWT =================
// block = one (b,c) row. Even/odd split arrays -> conflict-free stride-1 access.
// a[j] = e[j-1]dl1 + e[j]dl3 + e[j+1]dl5 + e[j+2]dl7 + o[j-2]dl0 + o[j-1]dl2 + o[j]dl4 + o[j+1]dl6
#define DWT_SMEM_F (2*4104 + 2*2056 + 2*1032)

__device__ __forceinline__ void dwt_level(const float* __restrict__ E, const float* __restrict__ O,
                                          int Lh, float* __restrict__ dOut,
                                          float* EO, float* OO, float* aOut) {
    for (int j = threadIdx.x; j < Lh; j += 256) {
        const float* e = E + 4 + j;
        const float* o = O + 4 + j;
        float a, d;
        a = e[-1]*c_dec_lo[1]; a = fmaf(e[0], c_dec_lo[3], a); a = fmaf(e[1], c_dec_lo[5], a);
        a = fmaf(e[2], c_dec_lo[7], a); a = fmaf(o[-2], c_dec_lo[0], a); a = fmaf(o[-1], c_dec_lo[2], a);
        a = fmaf(o[0], c_dec_lo[4], a); a = fmaf(o[1], c_dec_lo[6], a);
        d = e[-1]*c_dec_hi[1]; d = fmaf(e[0], c_dec_hi[3], d); d = fmaf(e[1], c_dec_hi[5], d);
        d = fmaf(e[2], c_dec_hi[7], d); d = fmaf(o[-2], c_dec_hi[0], d); d = fmaf(o[-1], c_dec_hi[2], d);
        d = fmaf(o[0], c_dec_hi[4], d); d = fmaf(o[1], c_dec_hi[6], d);
        dOut[j] = d;
        if (aOut) aOut[j] = a;
        else { if (j & 1) OO[4 + (j >> 1)] = a; else EO[4 + (j >> 1)] = a; }
    }
}

__global__ __launch_bounds__(256) void fused_dwt(const float* __restrict__ x,
                                                 float* __restrict__ D1,
                                                 float* __restrict__ D2,
                                                 float* __restrict__ D3,
                                                 float* __restrict__ A3) {
    extern __shared__ float sm[];
    float* E1 = sm;            // 4104
    float* O1 = sm + 4104;
    float* E2 = sm + 8208;     // 2056
    float* O2 = sm + 10264;
    float* E3 = sm + 12320;    // 1032
    float* O3 = sm + 13352;
    int row = blockIdx.x, tid = threadIdx.x;

    if (tid < 48) {            // zero 4-elem pads on both ends of 6 arrays
        int a = tid >> 3, p = tid & 7;
        float* bases[6] = {E1, O1, E2, O2, E3, O3};
        int lens[6] = {4096, 4096, 2048, 2048, 1024, 1024};
        bases[a][p < 4 ? p : lens[a] + p] = 0.f;   // [0..3] and [len+4..len+7]
    }
    const float4* x4 = (const float4*)(x + (size_t)row * 8192);
    for (int i = tid; i < 2048; i += 256) {
        float4 v = x4[i];
        E1[4 + 2*i] = v.x; O1[4 + 2*i] = v.y;
        E1[5 + 2*i] = v.z; O1[5 + 2*i] = v.w;
    }
    __syncthreads();
    dwt_level(E1, O1, 4096, D1 + (size_t)row * 4096, E2, O2, nullptr);
    __syncthreads();
    dwt_level(E2, O2, 2048, D2 + (size_t)row * 2048, E3, O3, nullptr);
    __syncthreads();
    dwt_level(E3, O3, 1024, D3 + (size_t)row * 1024, nullptr, nullptr, A3 + (size_t)row * 1024);
}

// ================= fused 3-level IDWT + skip =================
// y[2m]   = a[m-2]rl7 + a[m-1]rl5 + a[m]rl3 + a[m+1]rl1 + (d: rh same idx)
// y[2m+1] = a[m-1]rl6 + a[m]rl4 + a[m+1]rl2 + a[m+2]rl0 + (d: rh same idx)
#define IDWT_SMEM_F (2*1032 + 2*2056 + 2*4104)

__device__ __forceinline__ void idwt_level(const float* __restrict__ A, const float* __restrict__ D,
                                           int Lh, float* __restrict__ Y) {
    for (int m = threadIdx.x; m < Lh; m += 256) {
        const float* a = A + 4 + m;
        const float* d = D + 4 + m;
        float ye, yo;
        ye = a[-2]*c_rec_lo[7]; ye = fmaf(a[-1], c_rec_lo[5], ye); ye = fmaf(a[0], c_rec_lo[3], ye);
        ye = fmaf(a[1], c_rec_lo[1], ye); ye = fmaf(d[-2], c_rec_hi[7], ye); ye = fmaf(d[-1], c_rec_hi[5], ye);
        ye = fmaf(d[0], c_rec_hi[3], ye); ye = fmaf(d[1], c_rec_hi[1], ye);
        yo = a[-1]*c_rec_lo[6]; yo = fmaf(a[0], c_rec_lo[4], yo); yo = fmaf(a[1], c_rec_lo[2], yo);
        yo = fmaf(a[2], c_rec_lo[0], yo); yo = fmaf(d[-1], c_rec_hi[6], yo); yo = fmaf(d[0], c_rec_hi[4], yo);
        yo = fmaf(d[1], c_rec_hi[2], yo); yo = fmaf(d[2], c_rec_hi[0], yo);
        Y[4 + 2*m] = ye;
        Y[5 + 2*m] = yo;
    }
}

__global__ __launch_bounds__(256) void fused_idwt(const float* __restrict__ A3v,
                                                  const float* __restrict__ D3v,
                                                  const float* __restrict__ D2v,
                                                  const float* __restrict__ D1v,
                                                  const float* __restrict__ x,
                                                  float* __restrict__ S) {
    extern __shared__ float sm[];
    float* A3s = sm;             // 1032
    float* D3s = sm + 1032;
    float* Y2  = sm + 2064;      // 2056
    float* D2s = sm + 4120;
    float* Y1  = sm + 6176;      // 4104
    float* D1s = sm + 10280;
    int row = blockIdx.x, tid = threadIdx.x;

    if (tid < 48) {
        int a = tid >> 3, p = tid & 7;
        float* bases[6] = {A3s, D3s, Y2, D2s, Y1, D1s};
        int lens[6] = {1024, 1024, 2048, 2048, 4096, 4096};
        bases[a][p < 4 ? p : lens[a] + p] = 0.f;
    }
    {
        const float4* a3 = (const float4*)(A3v + (size_t)row * 1024);
        const float4* d3 = (const float4*)(D3v + (size_t)row * 1024);
        const float4* d2 = (const float4*)(D2v + (size_t)row * 2048);
        const float4* d1 = (const float4*)(D1v + (size_t)row * 4096);
        { float4 v = a3[tid]; *(float4*)&A3s[4 + 4*tid] = v; }
        { float4 v = d3[tid]; *(float4*)&D3s[4 + 4*tid] = v; }
        for (int i = tid; i < 512;  i += 256) { float4 v = d2[i]; *(float4*)&D2s[4 + 4*i] = v; }
        for (int i = tid; i < 1024; i += 256) { float4 v = d1[i]; *(float4*)&D1s[4 + 4*i] = v; }
    }
    __syncthreads();
    idwt_level(A3s, D3s, 1024, Y2);
    __syncthreads();
    idwt_level(Y2, D2s, 2048, Y1);
    __syncthreads();
    // last level fused with skip add, straight to gmem
    const float* xr = x + (size_t)row * 8192;
    float* Sr = S + (size_t)row * 8192;
    for (int m = tid; m < 4096; m += 256) {
        const float* a = Y1 + 4 + m;
        const float* d = D1s + 4 + m;
        float ye, yo;
        ye = a[-2]*c_rec_lo[7]; ye = fmaf(a[-1], c_rec_lo[5], ye); ye = fmaf(a[0], c_rec_lo[3], ye);
        ye = fmaf(a[1], c_rec_lo[1], ye); ye = fmaf(d[-2], c_rec_hi[7], ye); ye = fmaf(d[-1], c_rec_hi[5], ye);
        ye = fmaf(d[0], c_rec_hi[3], ye); ye = fmaf(d[1], c_rec_hi[1], ye);
        yo = a[-1]*c_rec_lo[6]; yo = fmaf(a[0], c_rec_lo[4], yo); yo = fmaf(a[1], c_rec_lo[2], yo);
        yo = fmaf(a[2], c_rec_lo[0], yo); yo = fmaf(d[-1], c_rec_hi[6], yo); yo = fmaf(d[0], c_rec_hi[4], yo);
        yo = fmaf(d[1], c_rec_hi[2], yo); yo = fmaf(d[2], c_rec_hi[0], yo);
        float2 xv = *(const float2*)&xr[2*m];
        *(float2*)&Sr[2*m] = make_float2(ye + xv.x, yo + xv.y);
    }
}

// ================= fused res block (two GEMMs + GELU + residual) =================
// CTA: M=256 (all channels), N=128 cols, K=256. 512 threads = 16 warps (4x4 warp grid).
// Phase 1: H = gelu(W1 @ X + b1) -> smem (XOR-swizzled [n][k]).
// Phase 2: Out = X + W2 @ H + b2.
// smem: A stages 2x32KB (XOR swizzle), B stages 2x17408B (pad 136), H 128KB. Total 231424B.
#define RES_SMEM (2*32768 + 2*17408 + 131072)

__global__ __launch_bounds__(512, 1) void resblock_fused(const float* __restrict__ X,
                                                         const float* __restrict__ W1,
                                                         const float* __restrict__ b1v,
                                                         const float* __restrict__ W2,
                                                         const float* __restrict__ b2v,
                                                         float* __restrict__ Out,
                                                         int L) {
    extern __shared__ float sm[];
    float* As = sm;                      // 2 * 8192 floats
    float* Bs = sm + 16384;              // 2 * 4352 floats
    float* Hs = sm + 16384 + 8704;       // 32768 floats
    uint32_t As_u = smem_u32(As);
    uint32_t Bs_u = smem_u32(Bs);

    int tid = threadIdx.x;
    int wid = tid >> 5, lane = tid & 31;
    int wm = wid >> 2;       // 0..3 : 64 rows
    int wn = wid & 3;        // 0..3 : 32 cols
    int g = lane >> 2, tt = lane & 3;
    int b = blockIdx.z;
    int ln = blockIdx.x * 128;
    const float* Xb = X + (size_t)b * NC * L + ln;

    auto load_chunk = [&](int i, int s) {
        const float* wsrc = (i < 8 ? W1 : W2) + (i & 7) * 32;
        uint32_t Ab = As_u + s * 32768;
#pragma unroll
        for (int q = 0; q < 4; q++) {
            int idx = tid + q * 512;
            int r = idx >> 3, c4 = (idx & 7) * 4;
            cp16(Ab + 4u * (r * 32 + (c4 ^ ((r & 7) * 4))), wsrc + (size_t)r * NC + c4);
        }
        if (i < 8) {
            uint32_t Bb = Bs_u + s * 17408;
            const float* isrc = Xb + (size_t)(i * 32) * L;
#pragma unroll
            for (int q = 0; q < 2; q++) {
                int idx = tid + q * 512;
                int k = idx >> 5, n4 = (idx & 31) * 4;
                cp16(Bb + 4u * (k * 136 + n4), isrc + (size_t)k * L + n4);
            }
        }
    };

    float acc[4][4][4];
#pragma unroll
    for (int mt = 0; mt < 4; mt++)
#pragma unroll
        for (int nt = 0; nt < 4; nt++)
#pragma unroll
            for (int r = 0; r < 4; r++) acc[mt][nt][r] = 0.f;

    load_chunk(0, 0); cp_commit();
    load_chunk(1, 1); cp_commit();

    // ---- phase 1: acc = W1 @ X ----
#pragma unroll 1
    for (int t = 0; t < 8; t++) {
        int s = t & 1;
        cp_wait1(); __syncthreads();
        const float* Aw = As + s * 8192;
        const float* Bw = Bs + s * 4352;
#pragma unroll
        for (int kk = 0; kk < 4; kk++) {
            int k = kk * 8 + tt;
            int x0 = k ^ (g * 4), x1 = (k + 4) ^ (g * 4);
            uint32_t a[4][4], bf[4][2];
#pragma unroll
            for (int mt = 0; mt < 4; mt++) {
                int r0 = (wm * 64 + mt * 16 + g) * 32;
                a[mt][0] = __float_as_uint(Aw[r0 + x0]);
                a[mt][1] = __float_as_uint(Aw[r0 + 256 + x0]);
                a[mt][2] = __float_as_uint(Aw[r0 + x1]);
                a[mt][3] = __float_as_uint(Aw[r0 + 256 + x1]);
            }
#pragma unroll
            for (int nt = 0; nt < 4; nt++) {
                int n = wn * 32 + nt * 8 + g;
                bf[nt][0] = to_tf32(Bw[k * 136 + n]);
                bf[nt][1] = to_tf32(Bw[(k + 4) * 136 + n]);
            }
#pragma unroll
            for (int mt = 0; mt < 4; mt++)
#pragma unroll
                for (int nt = 0; nt < 4; nt++)
                    mma_tf32(acc[mt][nt], a[mt], bf[nt]);
        }
        __syncthreads();
        load_chunk(t + 2, s);      // chunks 2..9 (8,9 = first W2 chunks)
        cp_commit();
    }

    // ---- gelu + write H to smem, reset acc ----
#pragma unroll
    for (int mt = 0; mt < 4; mt++)
#pragma unroll
        for (int half = 0; half < 2; half++) {
            int kr = wm * 64 + mt * 16 + g + half * 8;
            float bb = b1v[kr];
#pragma unroll
            for (int nt = 0; nt < 4; nt++)
#pragma unroll
                for (int bit = 0; bit < 2; bit++) {
                    int n = wn * 32 + nt * 8 + tt * 2 + bit;
                    Hs[n * 256 + (kr ^ ((n & 7) * 4))] =
                        gelu_tanh(acc[mt][nt][half * 2 + bit] + bb);
                    acc[mt][nt][half * 2 + bit] = 0.f;
                }
        }

    // ---- phase 2: acc = W2 @ H ----
#pragma unroll 1
    for (int t = 0; t < 8; t++) {
        int s = t & 1;
        cp_wait1(); __syncthreads();    // also orders Hs writes before reads (t=0)
        const float* Aw = As + s * 8192;
#pragma unroll
        for (int kk = 0; kk < 4; kk++) {
            int k = kk * 8 + tt;
            int kg = t * 32 + k;
            int x0 = k ^ (g * 4), x1 = (k + 4) ^ (g * 4);
            uint32_t a[4][4], bf[4][2];
#pragma unroll
            for (int mt = 0; mt < 4; mt++) {
                int r0 = (wm * 64 + mt * 16 + g) * 32;
                a[mt][0] = __float_as_uint(Aw[r0 + x0]);
                a[mt][1] = __float_as_uint(Aw[r0 + 256 + x0]);
                a[mt][2] = __float_as_uint(Aw[r0 + x1]);
                a[mt][3] = __float_as_uint(Aw[r0 + 256 + x1]);
            }
#pragma unroll
            for (int nt = 0; nt < 4; nt++) {
                int n = wn * 32 + nt * 8 + g;
                int xr = (n & 7) * 4;
                bf[nt][0] = to_tf32(Hs[n * 256 + (kg ^ xr)]);
                bf[nt][1] = to_tf32(Hs[n * 256 + ((kg + 4) ^ xr)]);
            }
#pragma unroll
            for (int mt = 0; mt < 4; mt++)
#pragma unroll
                for (int nt = 0; nt < 4; nt++)
                    mma_tf32(acc[mt][nt], a[mt], bf[nt]);
        }
        __syncthreads();
        if (t < 6) load_chunk(t + 10, s);   // chunks 10..15 (W2)
        cp_commit();
    }

    // ---- epilogue: Out = X + acc + b2 ----
    float* Ob = Out + (size_t)b * NC * L + ln;
#pragma unroll
    for (int mt = 0; mt < 4; mt++)
#pragma unroll
        for (int half = 0; half < 2; half++) {
            int o = wm * 64 + mt * 16 + g + half * 8;
            float bb = b2v[o];
            size_t orow = (size_t)o * L;
#pragma unroll
            for (int nt = 0; nt < 4; nt++) {
                int col = wn * 32 + nt * 8 + tt * 2;
                float2 rr = *(const float2*)&Xb[orow + col];
                float v0 = acc[mt][nt][half * 2 + 0] + bb + rr.x;
                float v1 = acc[mt][nt][half * 2 + 1] + bb + rr.y;
                *(float2*)&Ob[orow + col] = make_float2(v0, v1);
            }
        }
}

// ---------------- LayerNorm over channels ----------------
__global__ __launch_bounds__(256) void ln_kernel(const float* __restrict__ S,
                                                 const float* __restrict__ g,
                                                 const float* __restrict__ bt,
                                                 float* __restrict__ out,
                                                 int L) {
    int b = blockIdx.y;
    int l0 = blockIdx.x * 64;
    int tx = threadIdx.x & 63;
    int ty = threadIdx.x >> 6;
    const float* Sb = S + (size_t)b * NC * L + l0;
    float sum = 0.f, sq = 0.f;
    for (int c = ty; c < NC; c += 4) {
        float v = Sb[(size_t)c * L + tx];
        sum += v;
        sq = fmaf(v, v, sq);
    }
    __shared__ float ssum[4][64], ssq[4][64];
    __shared__ float smu[64], srs[64];
    ssum[ty][tx] = sum;
    ssq[ty][tx] = sq;
    __syncthreads();
    if (ty == 0) {
        float s = ssum[0][tx] + ssum[1][tx] + ssum[2][tx] + ssum[3][tx];
        float q = ssq[0][tx] + ssq[1][tx] + ssq[2][tx] + ssq[3][tx];
        float mu = s * (1.f / NC);
        float var = q * (1.f / NC) - mu * mu;
        smu[tx] = mu;
        srs[tx] = rsqrtf(var + 1e-5f);
    }
    __syncthreads();
    float* Ob = out + (size_t)b * NC * L + l0;
    float mu = smu[tx], rs = srs[tx];
    for (int c = ty; c < NC; c += 4) {
        float v = Sb[(size_t)c * L + tx];
        Ob[(size_t)c * L + tx] = (v - mu) * rs * g[c] + bt[c];
    }
}

// ---------------- launch ----------------
static float* sym_addr(const void* sym) {
    void* p = nullptr;
    cudaGetSymbolAddress(&p, sym);
    return (float*)p;
}

extern "C" void kernel_launch(void* const* d_in, const int* in_sizes, int n_in,
                              void* d_out, int out_size) {
    const float* x     = (const float*)d_in[0];
    const float* ab_w1 = (const float*)d_in[1];
    const float* ab_b1 = (const float*)d_in[2];
    const float* ab_w2 = (const float*)d_in[3];
    const float* ab_b2 = (const float*)d_in[4];
    const float* db_w1 = (const float*)d_in[5];
    const float* db_b1 = (const float*)d_in[6];
    const float* db_w2 = (const float*)d_in[7];
    const float* db_b2 = (const float*)d_in[8];
    const float* ln_g  = (const float*)d_in[9];
    const float* ln_b  = (const float*)d_in[10];
    float* out = (float*)d_out;

    float* D1 = sym_addr(g_D1);
    float* D2 = sym_addr(g_D2);
    float* D3 = sym_addr(g_D3);
    float* A3 = sym_addr(g_A3);
    float* S  = sym_addr(g_S);
    float* Wr = sym_addr(g_Wr);

    cudaFuncSetAttribute(resblock_fused, cudaFuncAttributeMaxDynamicSharedMemorySize, RES_SMEM);
    cudaFuncSetAttribute(fused_dwt,  cudaFuncAttributeMaxDynamicSharedMemorySize, DWT_SMEM_F * 4);
    cudaFuncSetAttribute(fused_idwt, cudaFuncAttributeMaxDynamicSharedMemorySize, IDWT_SMEM_F * 4);

    const int ROWS = NB * NC;   // 4096

    roundw_kernel<<<64, 256>>>(ab_w1, ab_w2, db_w1, db_w2, Wr);

    // fused forward DWT (3 levels, one launch)
    fused_dwt<<<ROWS, 256, DWT_SMEM_F * 4>>>(x, D1, D2, D3, A3);

    // fused res blocks (GEMM1 + GELU + GEMM2 + residual, in-place)
    auto resblock = [&](float* Xp, const float* w1r, const float* b1,
                        const float* w2r, const float* b2, int L) {
        dim3 grid(L / 128, 1, NB);
        resblock_fused<<<grid, 512, RES_SMEM>>>(Xp, w1r, b1, w2r, b2, Xp, L);
    };
    resblock(D3, Wr + 2*NC*NC, db_b1, Wr + 3*NC*NC, db_b2, 1024);
    resblock(D2, Wr + 2*NC*NC, db_b1, Wr + 3*NC*NC, db_b2, 2048);
    resblock(D1, Wr + 2*NC*NC, db_b1, Wr + 3*NC*NC, db_b2, 4096);
    resblock(A3, Wr + 0*NC*NC, ab_b1, Wr + 1*NC*NC, ab_b2, 1024);

    // fused inverse DWT (3 levels + skip add, one launch)
    fused_idwt<<<ROWS, 256, IDWT_SMEM_F * 4>>>(A3, D3, D2, D1, x, S);

    // layernorm over channels
    ln_kernel<<<dim3(8192 / 64, NB), 256>>>(S, ln_g, ln_b, out, 8192);
}

// round 5
// speedup vs baseline: 1.7201x; 1.7201x over previous
#include <cuda_runtime.h>
#include <cuda_fp16.h>
#include <cstdint>
#include <math.h>

#define NB 16
#define NC 256

// ---------------- scratch (device globals: no allocs allowed) ----------------
__device__ float g_D1[NB*NC*4096];
__device__ float g_D2[NB*NC*2048];
__device__ float g_D3[NB*NC*1024];
__device__ float g_A3[NB*NC*1024];
__device__ float g_S [NB*NC*8192];
__device__ __half g_Wh[4*NC*NC];    // fp16 weights: ab_w1, ab_w2, db_w1, db_w2

// ---------------- db4 filters ----------------
__constant__ float c_dec_lo[8] = {-0.010597401785069032f, 0.0328830116668852f, 0.030841381835560764f, -0.18703481171888114f, -0.027983769416859854f, 0.6308807679298589f, 0.7148465705529157f, 0.2303778133088965f};
__constant__ float c_dec_hi[8] = {-0.2303778133088965f, 0.7148465705529157f, -0.6308807679298589f, -0.027983769416859854f, 0.18703481171888114f, 0.030841381835560764f, -0.0328830116668852f, -0.010597401785069032f};
__constant__ float c_rec_lo[8] = {0.2303778133088965f, 0.7148465705529157f, 0.6308807679298589f, -0.027983769416859854f, -0.18703481171888114f, 0.030841381835560764f, 0.0328830116668852f, -0.010597401785069032f};
__constant__ float c_rec_hi[8] = {-0.010597401785069032f, -0.0328830116668852f, 0.030841381835560764f, 0.18703481171888114f, -0.027983769416859854f, -0.6308807679298589f, 0.7148465705529157f, -0.2303778133088965f};

// ================= helpers =================
__device__ __forceinline__ uint32_t smem_u32(const void* p) {
    uint32_t a;
    asm("{ .reg .u64 t; cvta.to.shared.u64 t, %1; cvt.u32.u64 %0, t; }" : "=r"(a) : "l"(p));
    return a;
}
__device__ __forceinline__ void cp16(uint32_t dst, const void* src) {
    asm volatile("cp.async.cg.shared.global [%0], [%1], 16;" :: "r"(dst), "l"(src));
}
__device__ __forceinline__ void cp_commit() { asm volatile("cp.async.commit_group;" ::: "memory"); }
__device__ __forceinline__ void cp_wait2()  { asm volatile("cp.async.wait_group 2;" ::: "memory"); }

__device__ __forceinline__ void mma_f16(float* c, const uint32_t* a, const uint32_t* b) {
    asm volatile("mma.sync.aligned.m16n8k16.row.col.f32.f16.f16.f32 "
                 "{%0,%1,%2,%3}, {%4,%5,%6,%7}, {%8,%9}, {%0,%1,%2,%3};"
                 : "+f"(c[0]), "+f"(c[1]), "+f"(c[2]), "+f"(c[3])
                 : "r"(a[0]), "r"(a[1]), "r"(a[2]), "r"(a[3]), "r"(b[0]), "r"(b[1]));
}
__device__ __forceinline__ void ldsm4(uint32_t* r, uint32_t addr) {
    asm volatile("ldmatrix.sync.aligned.m8n8.x4.shared.b16 {%0,%1,%2,%3}, [%4];"
                 : "=r"(r[0]), "=r"(r[1]), "=r"(r[2]), "=r"(r[3]) : "r"(addr));
}
__device__ __forceinline__ void ldsm4t(uint32_t* r, uint32_t addr) {
    asm volatile("ldmatrix.sync.aligned.m8n8.x4.trans.shared.b16 {%0,%1,%2,%3}, [%4];"
                 : "=r"(r[0]), "=r"(r[1]), "=r"(r[2]), "=r"(r[3]) : "r"(addr));
}
__device__ __forceinline__ float gelu_tanh(float x) {
    const float k0 = 0.7978845608028654f;
    const float k1 = 0.044715f;
    float x3 = x * x * x;
    float t = tanhf(k0 * (x + k1 * x3));
    return 0.5f * x * (1.f + t);
}

// ---------------- convert weights to fp16 ----------------
__global__ __launch_bounds__(256) void convw_kernel(const float* __restrict__ w0,
                                                    const float* __restrict__ w1,
                                                    const float* __restrict__ w2,
                                                    const float* __restrict__ w3,
                                                    __half* __restrict__ out) {
    int i = blockIdx.x * 256 + threadIdx.x;   // 16384 threads, one float4 per matrix
    const float* src[4] = {w0, w1, w2, w3};
#pragma unroll
    for (int m = 0; m < 4; m++) {
        float4 v = *(const float4*)(src[m] + i * 4);
        __half2 h0 = __floats2half2_rn(v.x, v.y);
        __half2 h1 = __floats2half2_rn(v.z, v.w);
        uint2 pk = make_uint2(*(uint32_t*)&h0, *(uint32_t*)&h1);
        *(uint2*)(out + m * 65536 + i * 4) = pk;
    }
}

// ================= fused 3-level DWT (pair-processing, 512 thr) =================
#define DWT_SMEM_F (2*4104 + 2*2056 + 2*1032)

__device__ __forceinline__ void dwt_level2(const float* __restrict__ E, const float* __restrict__ O,
                                           int Lh, float* __restrict__ dOut,
                                           float* EO, float* OO, float* aOut) {
    for (int i = threadIdx.x; i < (Lh >> 1); i += 512) {
        int j = 2 * i;
        const float* e = E + 4 + j;
        const float* o = O + 4 + j;
        float em1 = e[-1], e0 = e[0], e1 = e[1], e2 = e[2], e3 = e[3];
        float om2 = o[-2], om1 = o[-1], o0 = o[0], o1 = o[1], o2 = o[2];
        float a0 = em1*c_dec_lo[1] + e0*c_dec_lo[3] + e1*c_dec_lo[5] + e2*c_dec_lo[7]
                 + om2*c_dec_lo[0] + om1*c_dec_lo[2] + o0*c_dec_lo[4] + o1*c_dec_lo[6];
        float a1 = e0*c_dec_lo[1] + e1*c_dec_lo[3] + e2*c_dec_lo[5] + e3*c_dec_lo[7]
                 + om1*c_dec_lo[0] + o0*c_dec_lo[2] + o1*c_dec_lo[4] + o2*c_dec_lo[6];
        float d0 = em1*c_dec_hi[1] + e0*c_dec_hi[3] + e1*c_dec_hi[5] + e2*c_dec_hi[7]
                 + om2*c_dec_hi[0] + om1*c_dec_hi[2] + o0*c_dec_hi[4] + o1*c_dec_hi[6];
        float d1 = e0*c_dec_hi[1] + e1*c_dec_hi[3] + e2*c_dec_hi[5] + e3*c_dec_hi[7]
                 + om1*c_dec_hi[0] + o0*c_dec_hi[2] + o1*c_dec_hi[4] + o2*c_dec_hi[6];
        *(float2*)&dOut[j] = make_float2(d0, d1);
        if (aOut) *(float2*)&aOut[j] = make_float2(a0, a1);
        else { EO[4 + i] = a0; OO[4 + i] = a1; }
    }
}

__global__ __launch_bounds__(512) void fused_dwt(const float* __restrict__ x,
                                                 float* __restrict__ D1,
                                                 float* __restrict__ D2,
                                                 float* __restrict__ D3,
                                                 float* __restrict__ A3) {
    extern __shared__ float sm[];
    float* E1 = sm;            // 4104
    float* O1 = sm + 4104;
    float* E2 = sm + 8208;     // 2056
    float* O2 = sm + 10264;
    float* E3 = sm + 12320;    // 1032
    float* O3 = sm + 13352;
    int row = blockIdx.x, tid = threadIdx.x;

    if (tid < 48) {
        int a = tid >> 3, p = tid & 7;
        float* bases[6] = {E1, O1, E2, O2, E3, O3};
        int lens[6] = {4096, 4096, 2048, 2048, 1024, 1024};
        bases[a][p < 4 ? p : lens[a] + p] = 0.f;
    }
    const float4* x4 = (const float4*)(x + (size_t)row * 8192);
    for (int i = tid; i < 2048; i += 512) {
        float4 v = x4[i];
        E1[4 + 2*i] = v.x; O1[4 + 2*i] = v.y;
        E1[5 + 2*i] = v.z; O1[5 + 2*i] = v.w;
    }
    __syncthreads();
    dwt_level2(E1, O1, 4096, D1 + (size_t)row * 4096, E2, O2, nullptr);
    __syncthreads();
    dwt_level2(E2, O2, 2048, D2 + (size_t)row * 2048, E3, O3, nullptr);
    __syncthreads();
    dwt_level2(E3, O3, 1024, D3 + (size_t)row * 1024, nullptr, nullptr, A3 + (size_t)row * 1024);
}

// ================= fused 3-level IDWT + skip (512 thr) =================
#define IDWT_SMEM_F (2*1032 + 2*2056 + 2*4104)

__device__ __forceinline__ void idwt_level(const float* __restrict__ A, const float* __restrict__ D,
                                           int Lh, float* __restrict__ Y) {
    for (int m = threadIdx.x; m < Lh; m += 512) {
        const float* a = A + 4 + m;
        const float* d = D + 4 + m;
        float ye, yo;
        ye = a[-2]*c_rec_lo[7]; ye = fmaf(a[-1], c_rec_lo[5], ye); ye = fmaf(a[0], c_rec_lo[3], ye);
        ye = fmaf(a[1], c_rec_lo[1], ye); ye = fmaf(d[-2], c_rec_hi[7], ye); ye = fmaf(d[-1], c_rec_hi[5], ye);
        ye = fmaf(d[0], c_rec_hi[3], ye); ye = fmaf(d[1], c_rec_hi[1], ye);
        yo = a[-1]*c_rec_lo[6]; yo = fmaf(a[0], c_rec_lo[4], yo); yo = fmaf(a[1], c_rec_lo[2], yo);
        yo = fmaf(a[2], c_rec_lo[0], yo); yo = fmaf(d[-1], c_rec_hi[6], yo); yo = fmaf(d[0], c_rec_hi[4], yo);
        yo = fmaf(d[1], c_rec_hi[2], yo); yo = fmaf(d[2], c_rec_hi[0], yo);
        Y[4 + 2*m] = ye;
        Y[5 + 2*m] = yo;
    }
}

__global__ __launch_bounds__(512) void fused_idwt(const float* __restrict__ A3v,
                                                  const float* __restrict__ D3v,
                                                  const float* __restrict__ D2v,
                                                  const float* __restrict__ D1v,
                                                  const float* __restrict__ x,
                                                  float* __restrict__ S) {
    extern __shared__ float sm[];
    float* A3s = sm;             // 1032
    float* D3s = sm + 1032;
    float* Y2  = sm + 2064;      // 2056
    float* D2s = sm + 4120;
    float* Y1  = sm + 6176;      // 4104
    float* D1s = sm + 10280;
    int row = blockIdx.x, tid = threadIdx.x;

    if (tid < 48) {
        int a = tid >> 3, p = tid & 7;
        float* bases[6] = {A3s, D3s, Y2, D2s, Y1, D1s};
        int lens[6] = {1024, 1024, 2048, 2048, 4096, 4096};
        bases[a][p < 4 ? p : lens[a] + p] = 0.f;
    }
    {
        const float4* a3 = (const float4*)(A3v + (size_t)row * 1024);
        const float4* d3 = (const float4*)(D3v + (size_t)row * 1024);
        const float4* d2 = (const float4*)(D2v + (size_t)row * 2048);
        const float4* d1 = (const float4*)(D1v + (size_t)row * 4096);
        if (tid < 256) {
            { float4 v = a3[tid]; *(float4*)&A3s[4 + 4*tid] = v; }
            { float4 v = d3[tid]; *(float4*)&D3s[4 + 4*tid] = v; }
        }
        { float4 v = d2[tid]; *(float4*)&D2s[4 + 4*tid] = v; }
        for (int i = tid; i < 1024; i += 512) { float4 v = d1[i]; *(float4*)&D1s[4 + 4*i] = v; }
    }
    __syncthreads();
    idwt_level(A3s, D3s, 1024, Y2);
    __syncthreads();
    idwt_level(Y2, D2s, 2048, Y1);
    __syncthreads();
    const float* xr = x + (size_t)row * 8192;
    float* Sr = S + (size_t)row * 8192;
    for (int m = tid; m < 4096; m += 512) {
        const float* a = Y1 + 4 + m;
        const float* d = D1s + 4 + m;
        float ye, yo;
        ye = a[-2]*c_rec_lo[7]; ye = fmaf(a[-1], c_rec_lo[5], ye); ye = fmaf(a[0], c_rec_lo[3], ye);
        ye = fmaf(a[1], c_rec_lo[1], ye); ye = fmaf(d[-2], c_rec_hi[7], ye); ye = fmaf(d[-1], c_rec_hi[5], ye);
        ye = fmaf(d[0], c_rec_hi[3], ye); ye = fmaf(d[1], c_rec_hi[1], ye);
        yo = a[-1]*c_rec_lo[6]; yo = fmaf(a[0], c_rec_lo[4], yo); yo = fmaf(a[1], c_rec_lo[2], yo);
        yo = fmaf(a[2], c_rec_lo[0], yo); yo = fmaf(d[-1], c_rec_hi[6], yo); yo = fmaf(d[0], c_rec_hi[4], yo);
        yo = fmaf(d[1], c_rec_hi[2], yo); yo = fmaf(d[2], c_rec_hi[0], yo);
        float2 xv = *(const float2*)&xr[2*m];
        *(float2*)&Sr[2*m] = make_float2(ye + xv.x, yo + xv.y);
    }
}

// ================= combined fused res blocks, fp16 mma =================
// One launch: 1024 CTAs over {D3, A3, D2, D1} x 16 batches x n-tiles of 128.
// CTA: M=256, N=128, K=256. 16 warps (4x4), warp tile m64 x n32.
// Phase 1 (chunks 0-7):  acc = W1 @ X  (B from gmem fp32 -> fp16 smem)
//   GELU -> H (fp16 smem [k 256][n 128], pitch 272B)
// Phase 2 (chunks 8-15): acc = W2 @ H ; epilogue Out = X + acc + b2.
// A: fp16 [256 m][32 k] pitch 80B, 4 stages. B: fp16 [32 k][128 n] pitch 272B, 4 stages.
#define A_STAGE_B (256*80)      // 20480
#define B_STAGE_B (32*272)      // 8704
#define H_BYTES   (256*272)     // 69632
#define RS_SMEM   (4*A_STAGE_B + 4*B_STAGE_B + H_BYTES)   // 186368

__global__ __launch_bounds__(512, 1) void resblock_all(
        float* __restrict__ D3, float* __restrict__ A3,
        float* __restrict__ D2, float* __restrict__ D1,
        const __half* __restrict__ Wh,
        const float* __restrict__ ab_b1, const float* __restrict__ ab_b2,
        const float* __restrict__ db_b1, const float* __restrict__ db_b2) {
    extern __shared__ char smem[];
    uint32_t sA = smem_u32(smem);
    uint32_t sB = sA + 4 * A_STAGE_B;
    uint32_t sH = sB + 4 * B_STAGE_B;

    int tid = threadIdx.x;
    int wid = tid >> 5, lane = tid & 31;
    int wm = wid >> 2, wn = wid & 3;
    int g = lane >> 2, tt = lane & 3;
    int l15 = lane & 15, lhi = (lane >> 4) << 4;

    int id = blockIdx.x;
    int b = id >> 6, slot = id & 63;
    float* X; int L, ln;
    const __half *W1, *W2; const float *b1, *b2;
    if (slot < 8)       { X = D3; L = 1024; ln = slot * 128;        W1 = Wh + 2*65536; W2 = Wh + 3*65536; b1 = db_b1; b2 = db_b2; }
    else if (slot < 16) { X = A3; L = 1024; ln = (slot - 8) * 128;  W1 = Wh + 0*65536; W2 = Wh + 1*65536; b1 = ab_b1; b2 = ab_b2; }
    else if (slot < 32) { X = D2; L = 2048; ln = (slot - 16) * 128; W1 = Wh + 2*65536; W2 = Wh + 3*65536; b1 = db_b1; b2 = db_b2; }
    else                { X = D1; L = 4096; ln = (slot - 32) * 128; W1 = Wh + 2*65536; W2 = Wh + 3*65536; b1 = db_b1; b2 = db_b2; }
    float* Xb = X + (size_t)b * NC * L + ln;

    float acc[4][4][4];
#pragma unroll
    for (int mt = 0; mt < 4; mt++)
#pragma unroll
        for (int nt = 0; nt < 4; nt++)
#pragma unroll
            for (int r = 0; r < 4; r++) acc[mt][nt][r] = 0.f;

    auto loadA = [&](int c, int s) {
        const __half* wsrc = (c < 8 ? W1 : W2) + (c & 7) * 32;
#pragma unroll
        for (int q = 0; q < 2; q++) {
            int idx = tid + q * 512;
            int r = idx >> 2, u = idx & 3;
            cp16(sA + s * A_STAGE_B + r * 80 + u * 16, wsrc + r * 256 + u * 8);
        }
    };
    float4 breg[2];
    auto ldgB = [&](int c) {
#pragma unroll
        for (int q = 0; q < 2; q++) {
            int idx = tid + q * 512;
            int k = idx >> 5, n4 = (idx & 31) * 4;
            breg[q] = *(const float4*)(Xb + (size_t)(c * 32 + k) * L + n4);
        }
    };
    auto stsB = [&](int s) {
#pragma unroll
        for (int q = 0; q < 2; q++) {
            int idx = tid + q * 512;
            int k = idx >> 5, n4 = (idx & 31) * 4;
            __half2 h0 = __floats2half2_rn(breg[q].x, breg[q].y);
            __half2 h1 = __floats2half2_rn(breg[q].z, breg[q].w);
            asm volatile("st.shared.v2.b32 [%0], {%1,%2};"
                         :: "r"(sB + s * B_STAGE_B + k * 272 + n4 * 2),
                            "r"(*(uint32_t*)&h0), "r"(*(uint32_t*)&h1));
        }
    };
    auto compute = [&](int c, int s) {
        uint32_t Abase = sA + s * A_STAGE_B + (wm * 64) * 80;
        uint32_t Bbase = (c < 8) ? (sB + s * B_STAGE_B) : (sH + (uint32_t)(c - 8) * 32 * 272);
#pragma unroll
        for (int kk = 0; kk < 2; kk++) {
            uint32_t a[4][4];
#pragma unroll
            for (int mt = 0; mt < 4; mt++)
                ldsm4(a[mt], Abase + (mt * 16 + l15) * 80 + kk * 32 + lhi);
            uint32_t bf[2][4];
#pragma unroll
            for (int p = 0; p < 2; p++)
                ldsm4t(bf[p], Bbase + (kk * 16 + l15) * 272 + (wn * 32 + p * 16) * 2 + lhi);
#pragma unroll
            for (int mt = 0; mt < 4; mt++)
#pragma unroll
                for (int nt = 0; nt < 4; nt++)
                    mma_f16(acc[mt][nt], a[mt], &bf[nt >> 1][(nt & 1) * 2]);
        }
    };

    // prologue
    loadA(0, 0); cp_commit();
    loadA(1, 1); cp_commit();
    loadA(2, 2); cp_commit();
    ldgB(0); stsB(0);
    ldgB(1);

#pragma unroll 1
    for (int c = 0; c < 16; c++) {
        int s = c & 3;
        cp_wait2();
        __syncthreads();
        if (c + 1 < 8) stsB((c + 1) & 3);
        if (c + 2 < 8) ldgB(c + 2);
        if (c + 3 < 16) loadA(c + 3, (c + 3) & 3);
        cp_commit();
        compute(c, s);
        if (c == 7) {
            // GELU -> H, reset acc
#pragma unroll
            for (int mt = 0; mt < 4; mt++)
#pragma unroll
                for (int hh = 0; hh < 2; hh++) {
                    int m = wm * 64 + mt * 16 + g + hh * 8;
                    float bb = b1[m];
#pragma unroll
                    for (int nt = 0; nt < 4; nt++) {
                        float v0 = gelu_tanh(acc[mt][nt][hh * 2 + 0] + bb);
                        float v1 = gelu_tanh(acc[mt][nt][hh * 2 + 1] + bb);
                        __half2 h = __floats2half2_rn(v0, v1);
                        asm volatile("st.shared.b32 [%0], %1;"
                                     :: "r"(sH + m * 272 + (wn * 32 + nt * 8 + tt * 2) * 2),
                                        "r"(*(uint32_t*)&h));
                        acc[mt][nt][hh * 2 + 0] = 0.f;
                        acc[mt][nt][hh * 2 + 1] = 0.f;
                    }
                }
        }
    }

    // ---- epilogue: X += acc + b2 ----
#pragma unroll
    for (int mt = 0; mt < 4; mt++)
#pragma unroll
        for (int hh = 0; hh < 2; hh++) {
            int m = wm * 64 + mt * 16 + g + hh * 8;
            float bb = b2[m];
            size_t orow = (size_t)m * L;
#pragma unroll
            for (int nt = 0; nt < 4; nt++) {
                int col = wn * 32 + nt * 8 + tt * 2;
                float2 rr = *(const float2*)&Xb[orow + col];
                *(float2*)&Xb[orow + col] =
                    make_float2(acc[mt][nt][hh * 2 + 0] + bb + rr.x,
                                acc[mt][nt][hh * 2 + 1] + bb + rr.y);
            }
        }
}

// ---------------- LayerNorm over channels ----------------
__global__ __launch_bounds__(256) void ln_kernel(const float* __restrict__ S,
                                                 const float* __restrict__ g,
                                                 const float* __restrict__ bt,
                                                 float* __restrict__ out,
                                                 int L) {
    int b = blockIdx.y;
    int l0 = blockIdx.x * 64;
    int tx = threadIdx.x & 63;
    int ty = threadIdx.x >> 6;
    const float* Sb = S + (size_t)b * NC * L + l0;
    float sum = 0.f, sq = 0.f;
    for (int c = ty; c < NC; c += 4) {
        float v = Sb[(size_t)c * L + tx];
        sum += v;
        sq = fmaf(v, v, sq);
    }
    __shared__ float ssum[4][64], ssq[4][64];
    __shared__ float smu[64], srs[64];
    ssum[ty][tx] = sum;
    ssq[ty][tx] = sq;
    __syncthreads();
    if (ty == 0) {
        float s = ssum[0][tx] + ssum[1][tx] + ssum[2][tx] + ssum[3][tx];
        float q = ssq[0][tx] + ssq[1][tx] + ssq[2][tx] + ssq[3][tx];
        float mu = s * (1.f / NC);
        float var = q * (1.f / NC) - mu * mu;
        smu[tx] = mu;
        srs[tx] = rsqrtf(var + 1e-5f);
    }
    __syncthreads();
    float* Ob = out + (size_t)b * NC * L + l0;
    float mu = smu[tx], rs = srs[tx];
    for (int c = ty; c < NC; c += 4) {
        float v = Sb[(size_t)c * L + tx];
        Ob[(size_t)c * L + tx] = (v - mu) * rs * g[c] + bt[c];
    }
}

// ---------------- launch ----------------
static float* sym_addr(const void* sym) {
    void* p = nullptr;
    cudaGetSymbolAddress(&p, sym);
    return (float*)p;
}

extern "C" void kernel_launch(void* const* d_in, const int* in_sizes, int n_in,
                              void* d_out, int out_size) {
    const float* x     = (const float*)d_in[0];
    const float* ab_w1 = (const float*)d_in[1];
    const float* ab_b1 = (const float*)d_in[2];
    const float* ab_w2 = (const float*)d_in[3];
    const float* ab_b2 = (const float*)d_in[4];
    const float* db_w1 = (const float*)d_in[5];
    const float* db_b1 = (const float*)d_in[6];
    const float* db_w2 = (const float*)d_in[7];
    const float* db_b2 = (const float*)d_in[8];
    const float* ln_g  = (const float*)d_in[9];
    const float* ln_b  = (const float*)d_in[10];
    float* out = (float*)d_out;

    float* D1 = sym_addr(g_D1);
    float* D2 = sym_addr(g_D2);
    float* D3 = sym_addr(g_D3);
    float* A3 = sym_addr(g_A3);
    float* S  = sym_addr(g_S);
    __half* Wh = (__half*)sym_addr(g_Wh);

    cudaFuncSetAttribute(resblock_all, cudaFuncAttributeMaxDynamicSharedMemorySize, RS_SMEM);
    cudaFuncSetAttribute(fused_dwt,  cudaFuncAttributeMaxDynamicSharedMemorySize, DWT_SMEM_F * 4);
    cudaFuncSetAttribute(fused_idwt, cudaFuncAttributeMaxDynamicSharedMemorySize, IDWT_SMEM_F * 4);

    const int ROWS = NB * NC;   // 4096

    convw_kernel<<<64, 256>>>(ab_w1, ab_w2, db_w1, db_w2, Wh);

    fused_dwt<<<ROWS, 512, DWT_SMEM_F * 4>>>(x, D1, D2, D3, A3);

    resblock_all<<<1024, 512, RS_SMEM>>>(D3, A3, D2, D1, Wh,
                                         ab_b1, ab_b2, db_b1, db_b2);

    fused_idwt<<<ROWS, 512, IDWT_SMEM_F * 4>>>(A3, D3, D2, D1, x, S);

    ln_kernel<<<dim3(8192 / 64, NB), 256>>>(S, ln_g, ln_b, out, 8192);
}

// round 6
// speedup vs baseline: 1.7606x; 1.0235x over previous
#include <cuda_runtime.h>
#include <cuda_fp16.h>
#include <cstdint>
#include <math.h>

#define NB 16
#define NC 256

// ---------------- scratch (device globals: no allocs allowed) ----------------
__device__ __half g_D1[NB*NC*4096];
__device__ __half g_D2[NB*NC*2048];
__device__ __half g_D3[NB*NC*1024];
__device__ __half g_A3[NB*NC*1024];
__device__ float  g_S [NB*NC*8192];
__device__ __half g_Wh[4*NC*NC];    // fp16 weights: ab_w1, ab_w2, db_w1, db_w2

// ---------------- db4 filters ----------------
__constant__ float c_dec_lo[8] = {-0.010597401785069032f, 0.0328830116668852f, 0.030841381835560764f, -0.18703481171888114f, -0.027983769416859854f, 0.6308807679298589f, 0.7148465705529157f, 0.2303778133088965f};
__constant__ float c_dec_hi[8] = {-0.2303778133088965f, 0.7148465705529157f, -0.6308807679298589f, -0.027983769416859854f, 0.18703481171888114f, 0.030841381835560764f, -0.0328830116668852f, -0.010597401785069032f};
__constant__ float c_rec_lo[8] = {0.2303778133088965f, 0.7148465705529157f, 0.6308807679298589f, -0.027983769416859854f, -0.18703481171888114f, 0.030841381835560764f, 0.0328830116668852f, -0.010597401785069032f};
__constant__ float c_rec_hi[8] = {-0.010597401785069032f, -0.0328830116668852f, 0.030841381835560764f, 0.18703481171888114f, -0.027983769416859854f, -0.6308807679298589f, 0.7148465705529157f, -0.2303778133088965f};

// ================= helpers =================
__device__ __forceinline__ uint32_t smem_u32(const void* p) {
    uint32_t a;
    asm("{ .reg .u64 t; cvta.to.shared.u64 t, %1; cvt.u32.u64 %0, t; }" : "=r"(a) : "l"(p));
    return a;
}
__device__ __forceinline__ void cp16(uint32_t dst, const void* src) {
    asm volatile("cp.async.cg.shared.global [%0], [%1], 16;" :: "r"(dst), "l"(src));
}
__device__ __forceinline__ void cp_commit() { asm volatile("cp.async.commit_group;" ::: "memory"); }
__device__ __forceinline__ void cp_wait2()  { asm volatile("cp.async.wait_group 2;" ::: "memory"); }

__device__ __forceinline__ void mma_f16(float* c, const uint32_t* a, const uint32_t* b) {
    asm volatile("mma.sync.aligned.m16n8k16.row.col.f32.f16.f16.f32 "
                 "{%0,%1,%2,%3}, {%4,%5,%6,%7}, {%8,%9}, {%0,%1,%2,%3};"
                 : "+f"(c[0]), "+f"(c[1]), "+f"(c[2]), "+f"(c[3])
                 : "r"(a[0]), "r"(a[1]), "r"(a[2]), "r"(a[3]), "r"(b[0]), "r"(b[1]));
}
__device__ __forceinline__ void ldsm4(uint32_t* r, uint32_t addr) {
    asm volatile("ldmatrix.sync.aligned.m8n8.x4.shared.b16 {%0,%1,%2,%3}, [%4];"
                 : "=r"(r[0]), "=r"(r[1]), "=r"(r[2]), "=r"(r[3]) : "r"(addr));
}
__device__ __forceinline__ void ldsm4t(uint32_t* r, uint32_t addr) {
    asm volatile("ldmatrix.sync.aligned.m8n8.x4.trans.shared.b16 {%0,%1,%2,%3}, [%4];"
                 : "=r"(r[0]), "=r"(r[1]), "=r"(r[2]), "=r"(r[3]) : "r"(addr));
}
__device__ __forceinline__ float gelu_tanh(float x) {
    const float k0 = 0.7978845608028654f;
    const float k1 = 0.044715f;
    float x3 = x * x * x;
    float t = tanhf(k0 * (x + k1 * x3));
    return 0.5f * x * (1.f + t);
}

// ---------------- convert weights to fp16 ----------------
__global__ __launch_bounds__(256) void convw_kernel(const float* __restrict__ w0,
                                                    const float* __restrict__ w1,
                                                    const float* __restrict__ w2,
                                                    const float* __restrict__ w3,
                                                    __half* __restrict__ out) {
    int i = blockIdx.x * 256 + threadIdx.x;
    const float* src[4] = {w0, w1, w2, w3};
#pragma unroll
    for (int m = 0; m < 4; m++) {
        float4 v = *(const float4*)(src[m] + i * 4);
        __half2 h0 = __floats2half2_rn(v.x, v.y);
        __half2 h1 = __floats2half2_rn(v.z, v.w);
        uint2 pk = make_uint2(*(uint32_t*)&h0, *(uint32_t*)&h1);
        *(uint2*)(out + m * 65536 + i * 4) = pk;
    }
}

// ================= fused 3-level DWT =================
// level 1 reads x directly from gmem (L1 reuse), levels 2-3 via fp32 smem.
// Outputs D1,D2,D3,A3 in fp16.
#define DWT_SMEM_F (2*2056 + 2*1032)

__device__ __forceinline__ void dwt_level_h(const float* __restrict__ E, const float* __restrict__ O,
                                            int Lh, __half* __restrict__ dOut,
                                            float* EO, float* OO, __half* aOut) {
    for (int i = threadIdx.x; i < (Lh >> 1); i += 512) {
        int j = 2 * i;
        const float* e = E + 4 + j;
        const float* o = O + 4 + j;
        float em1 = e[-1], e0 = e[0], e1 = e[1], e2 = e[2], e3 = e[3];
        float om2 = o[-2], om1 = o[-1], o0 = o[0], o1 = o[1], o2 = o[2];
        float a0 = em1*c_dec_lo[1] + e0*c_dec_lo[3] + e1*c_dec_lo[5] + e2*c_dec_lo[7]
                 + om2*c_dec_lo[0] + om1*c_dec_lo[2] + o0*c_dec_lo[4] + o1*c_dec_lo[6];
        float a1 = e0*c_dec_lo[1] + e1*c_dec_lo[3] + e2*c_dec_lo[5] + e3*c_dec_lo[7]
                 + om1*c_dec_lo[0] + o0*c_dec_lo[2] + o1*c_dec_lo[4] + o2*c_dec_lo[6];
        float d0 = em1*c_dec_hi[1] + e0*c_dec_hi[3] + e1*c_dec_hi[5] + e2*c_dec_hi[7]
                 + om2*c_dec_hi[0] + om1*c_dec_hi[2] + o0*c_dec_hi[4] + o1*c_dec_hi[6];
        float d1 = e0*c_dec_hi[1] + e1*c_dec_hi[3] + e2*c_dec_hi[5] + e3*c_dec_hi[7]
                 + om1*c_dec_hi[0] + o0*c_dec_hi[2] + o1*c_dec_hi[4] + o2*c_dec_hi[6];
        *(__half2*)&dOut[j] = __floats2half2_rn(d0, d1);
        if (aOut) *(__half2*)&aOut[j] = __floats2half2_rn(a0, a1);
        else { EO[4 + i] = a0; OO[4 + i] = a1; }
    }
}

__global__ __launch_bounds__(512) void fused_dwt(const float* __restrict__ x,
                                                 __half* __restrict__ D1,
                                                 __half* __restrict__ D2,
                                                 __half* __restrict__ D3,
                                                 __half* __restrict__ A3) {
    extern __shared__ float sm[];
    float* E2 = sm;            // 2056
    float* O2 = sm + 2056;
    float* E3 = sm + 4112;     // 1032
    float* O3 = sm + 5144;
    int row = blockIdx.x, tid = threadIdx.x;

    if (tid < 32) {            // zero pads
        int a = tid >> 3, p = tid & 7;
        float* bases[4] = {E2, O2, E3, O3};
        int lens[4] = {2048, 2048, 1024, 1024};
        bases[a][p < 4 ? p : lens[a] + p] = 0.f;
    }
    __syncthreads();

    // ---- level 1: x (gmem) -> D1 (fp16), approx -> E2/O2 (fp32 smem) ----
    const float* xr = x + (size_t)row * 8192;
    __half* D1r = D1 + (size_t)row * 4096;
    for (int i = tid; i < 2048; i += 512) {
        int j = 2 * i;
        int base = 2 * j - 3;
        float v[10];
#pragma unroll
        for (int q = 0; q < 10; q++) {
            int idx = base + q;
            v[q] = ((unsigned)idx < 8192u) ? __ldg(xr + idx) : 0.f;
        }
        float a0 = 0.f, a1 = 0.f, d0 = 0.f, d1 = 0.f;
#pragma unroll
        for (int t = 0; t < 8; t++) {
            a0 = fmaf(v[t],     c_dec_lo[t], a0);
            a1 = fmaf(v[t + 2], c_dec_lo[t], a1);
            d0 = fmaf(v[t],     c_dec_hi[t], d0);
            d1 = fmaf(v[t + 2], c_dec_hi[t], d1);
        }
        *(__half2*)&D1r[j] = __floats2half2_rn(d0, d1);
        E2[4 + i] = a0;
        O2[4 + i] = a1;
    }
    __syncthreads();
    dwt_level_h(E2, O2, 2048, D2 + (size_t)row * 2048, E3, O3, nullptr);
    __syncthreads();
    dwt_level_h(E3, O3, 1024, D3 + (size_t)row * 1024, nullptr, nullptr, A3 + (size_t)row * 1024);
}

// ================= fused 3-level IDWT + skip =================
// inputs fp16 (converted to fp32 in smem); D1 read direct from gmem (L1 reuse).
#define IDWT_SMEM_F (2*1032 + 2*2056 + 4104)

__device__ __forceinline__ void idwt_level(const float* __restrict__ A, const float* __restrict__ D,
                                           int Lh, float* __restrict__ Y) {
    for (int m = threadIdx.x; m < Lh; m += 512) {
        const float* a = A + 4 + m;
        const float* d = D + 4 + m;
        float ye, yo;
        ye = a[-2]*c_rec_lo[7]; ye = fmaf(a[-1], c_rec_lo[5], ye); ye = fmaf(a[0], c_rec_lo[3], ye);
        ye = fmaf(a[1], c_rec_lo[1], ye); ye = fmaf(d[-2], c_rec_hi[7], ye); ye = fmaf(d[-1], c_rec_hi[5], ye);
        ye = fmaf(d[0], c_rec_hi[3], ye); ye = fmaf(d[1], c_rec_hi[1], ye);
        yo = a[-1]*c_rec_lo[6]; yo = fmaf(a[0], c_rec_lo[4], yo); yo = fmaf(a[1], c_rec_lo[2], yo);
        yo = fmaf(a[2], c_rec_lo[0], yo); yo = fmaf(d[-1], c_rec_hi[6], yo); yo = fmaf(d[0], c_rec_hi[4], yo);
        yo = fmaf(d[1], c_rec_hi[2], yo); yo = fmaf(d[2], c_rec_hi[0], yo);
        Y[4 + 2*m] = ye;
        Y[5 + 2*m] = yo;
    }
}

__global__ __launch_bounds__(512) void fused_idwt(const __half* __restrict__ A3v,
                                                  const __half* __restrict__ D3v,
                                                  const __half* __restrict__ D2v,
                                                  const __half* __restrict__ D1v,
                                                  const float* __restrict__ x,
                                                  float* __restrict__ S) {
    extern __shared__ float sm[];
    float* A3s = sm;             // 1032
    float* D3s = sm + 1032;
    float* Y2  = sm + 2064;      // 2056
    float* D2s = sm + 4120;
    float* Y1  = sm + 6176;      // 4104
    int row = blockIdx.x, tid = threadIdx.x;

    if (tid < 40) {
        int a = tid >> 3, p = tid & 7;
        float* bases[5] = {A3s, D3s, Y2, D2s, Y1};
        int lens[5] = {1024, 1024, 2048, 2048, 4096};
        bases[a][p < 4 ? p : lens[a] + p] = 0.f;
    }
    {
        const __half2* a3 = (const __half2*)(A3v + (size_t)row * 1024);
        const __half2* d3 = (const __half2*)(D3v + (size_t)row * 1024);
        const __half2* d2 = (const __half2*)(D2v + (size_t)row * 2048);
        { float2 f = __half22float2(a3[tid]); A3s[4 + 2*tid] = f.x; A3s[5 + 2*tid] = f.y; }
        { float2 f = __half22float2(d3[tid]); D3s[4 + 2*tid] = f.x; D3s[5 + 2*tid] = f.y; }
#pragma unroll
        for (int q = 0; q < 2; q++) {
            int i = tid + q * 512;
            float2 f = __half22float2(d2[i]);
            D2s[4 + 2*i] = f.x; D2s[5 + 2*i] = f.y;
        }
    }
    __syncthreads();
    idwt_level(A3s, D3s, 1024, Y2);
    __syncthreads();
    idwt_level(Y2, D2s, 2048, Y1);
    __syncthreads();
    // level 1 + skip add: a from Y1 smem, d from D1 gmem (fp16, L1 reuse)
    const __half* d1r = D1v + (size_t)row * 4096;
    const float* xr = x + (size_t)row * 8192;
    float* Sr = S + (size_t)row * 8192;
    for (int m = tid; m < 4096; m += 512) {
        const float* a = Y1 + 4 + m;
        float dm2 = (m >= 2)    ? __half2float(__ldg(d1r + m - 2)) : 0.f;
        float dm1 = (m >= 1)    ? __half2float(__ldg(d1r + m - 1)) : 0.f;
        float d0  =               __half2float(__ldg(d1r + m));
        float dp1 = (m <= 4094) ? __half2float(__ldg(d1r + m + 1)) : 0.f;
        float dp2 = (m <= 4093) ? __half2float(__ldg(d1r + m + 2)) : 0.f;
        float ye, yo;
        ye = a[-2]*c_rec_lo[7]; ye = fmaf(a[-1], c_rec_lo[5], ye); ye = fmaf(a[0], c_rec_lo[3], ye);
        ye = fmaf(a[1], c_rec_lo[1], ye); ye = fmaf(dm2, c_rec_hi[7], ye); ye = fmaf(dm1, c_rec_hi[5], ye);
        ye = fmaf(d0, c_rec_hi[3], ye); ye = fmaf(dp1, c_rec_hi[1], ye);
        yo = a[-1]*c_rec_lo[6]; yo = fmaf(a[0], c_rec_lo[4], yo); yo = fmaf(a[1], c_rec_lo[2], yo);
        yo = fmaf(a[2], c_rec_lo[0], yo); yo = fmaf(dm1, c_rec_hi[6], yo); yo = fmaf(d0, c_rec_hi[4], yo);
        yo = fmaf(dp1, c_rec_hi[2], yo); yo = fmaf(dp2, c_rec_hi[0], yo);
        float2 xv = *(const float2*)&xr[2*m];
        *(float2*)&Sr[2*m] = make_float2(ye + xv.x, yo + xv.y);
    }
}

// ================= combined fused res blocks, fp16 mma, fp16 activations =================
// One launch: 1024 CTAs over {D3, A3, D2, D1} x 16 batches x n-tiles of 128.
// CTA: M=256, N=128, K=256. 16 warps (4x4), warp tile m64 x n32.
// A: fp16 [256 m][32 k] pitch 80B, 4 stages (cp.async).
// B: fp16 [32 k][128 n] pitch 272B, 4 stages (cp.async direct from fp16 gmem).
// H: fp16 [256 k][128 n] pitch 272B.
#define A_STAGE_B (256*80)      // 20480
#define B_STAGE_B (32*272)      // 8704
#define H_BYTES   (256*272)     // 69632
#define RS_SMEM   (4*A_STAGE_B + 4*B_STAGE_B + H_BYTES)   // 186368

__global__ __launch_bounds__(512, 1) void resblock_all(
        __half* __restrict__ D3, __half* __restrict__ A3,
        __half* __restrict__ D2, __half* __restrict__ D1,
        const __half* __restrict__ Wh,
        const float* __restrict__ ab_b1, const float* __restrict__ ab_b2,
        const float* __restrict__ db_b1, const float* __restrict__ db_b2) {
    extern __shared__ char smem[];
    uint32_t sA = smem_u32(smem);
    uint32_t sB = sA + 4 * A_STAGE_B;
    uint32_t sH = sB + 4 * B_STAGE_B;

    int tid = threadIdx.x;
    int wid = tid >> 5, lane = tid & 31;
    int wm = wid >> 2, wn = wid & 3;
    int g = lane >> 2, tt = lane & 3;
    int l15 = lane & 15, lhi = (lane >> 4) << 4;

    int id = blockIdx.x;
    int b = id >> 6, slot = id & 63;
    __half* X; int L, ln;
    const __half *W1, *W2; const float *b1, *b2;
    if (slot < 8)       { X = D3; L = 1024; ln = slot * 128;        W1 = Wh + 2*65536; W2 = Wh + 3*65536; b1 = db_b1; b2 = db_b2; }
    else if (slot < 16) { X = A3; L = 1024; ln = (slot - 8) * 128;  W1 = Wh + 0*65536; W2 = Wh + 1*65536; b1 = ab_b1; b2 = ab_b2; }
    else if (slot < 32) { X = D2; L = 2048; ln = (slot - 16) * 128; W1 = Wh + 2*65536; W2 = Wh + 3*65536; b1 = db_b1; b2 = db_b2; }
    else                { X = D1; L = 4096; ln = (slot - 32) * 128; W1 = Wh + 2*65536; W2 = Wh + 3*65536; b1 = db_b1; b2 = db_b2; }
    __half* Xb = X + (size_t)b * NC * L + ln;

    float acc[4][4][4];
#pragma unroll
    for (int mt = 0; mt < 4; mt++)
#pragma unroll
        for (int nt = 0; nt < 4; nt++)
#pragma unroll
            for (int r = 0; r < 4; r++) acc[mt][nt][r] = 0.f;

    auto loadAB = [&](int c, int s) {
        const __half* wsrc = (c < 8 ? W1 : W2) + (c & 7) * 32;
#pragma unroll
        for (int q = 0; q < 2; q++) {
            int idx = tid + q * 512;
            int r = idx >> 2, u = idx & 3;
            cp16(sA + s * A_STAGE_B + r * 80 + u * 16, wsrc + r * 256 + u * 8);
        }
        if (c < 8) {
            int k = tid >> 4, u = tid & 15;
            cp16(sB + s * B_STAGE_B + k * 272 + u * 16,
                 Xb + (size_t)(c * 32 + k) * L + u * 8);
        }
    };
    auto compute = [&](int c, int s) {
        uint32_t Abase = sA + s * A_STAGE_B + (wm * 64) * 80;
        uint32_t Bbase = (c < 8) ? (sB + s * B_STAGE_B) : (sH + (uint32_t)(c - 8) * 32 * 272);
#pragma unroll
        for (int kk = 0; kk < 2; kk++) {
            uint32_t a[4][4];
#pragma unroll
            for (int mt = 0; mt < 4; mt++)
                ldsm4(a[mt], Abase + (mt * 16 + l15) * 80 + kk * 32 + lhi);
            uint32_t bf[2][4];
#pragma unroll
            for (int p = 0; p < 2; p++)
                ldsm4t(bf[p], Bbase + (kk * 16 + l15) * 272 + (wn * 32 + p * 16) * 2 + lhi);
#pragma unroll
            for (int mt = 0; mt < 4; mt++)
#pragma unroll
                for (int nt = 0; nt < 4; nt++)
                    mma_f16(acc[mt][nt], a[mt], &bf[nt >> 1][(nt & 1) * 2]);
        }
    };

    // prologue: 3 stages in flight
    loadAB(0, 0); cp_commit();
    loadAB(1, 1); cp_commit();
    loadAB(2, 2); cp_commit();

#pragma unroll 1
    for (int c = 0; c < 16; c++) {
        int s = c & 3;
        cp_wait2();
        __syncthreads();
        if (c + 3 < 16) loadAB(c + 3, (c + 3) & 3);
        cp_commit();
        compute(c, s);
        if (c == 7) {
            // GELU -> H (fp16 smem), reset acc
#pragma unroll
            for (int mt = 0; mt < 4; mt++)
#pragma unroll
                for (int hh = 0; hh < 2; hh++) {
                    int m = wm * 64 + mt * 16 + g + hh * 8;
                    float bb = b1[m];
#pragma unroll
                    for (int nt = 0; nt < 4; nt++) {
                        float v0 = gelu_tanh(acc[mt][nt][hh * 2 + 0] + bb);
                        float v1 = gelu_tanh(acc[mt][nt][hh * 2 + 1] + bb);
                        __half2 h = __floats2half2_rn(v0, v1);
                        asm volatile("st.shared.b32 [%0], %1;"
                                     :: "r"(sH + m * 272 + (wn * 32 + nt * 8 + tt * 2) * 2),
                                        "r"(*(uint32_t*)&h));
                        acc[mt][nt][hh * 2 + 0] = 0.f;
                        acc[mt][nt][hh * 2 + 1] = 0.f;
                    }
                }
        }
    }

    // ---- epilogue: X = X + acc + b2 (fp16 in-place) ----
#pragma unroll
    for (int mt = 0; mt < 4; mt++)
#pragma unroll
        for (int hh = 0; hh < 2; hh++) {
            int m = wm * 64 + mt * 16 + g + hh * 8;
            float bb = b2[m];
            size_t orow = (size_t)m * L;
#pragma unroll
            for (int nt = 0; nt < 4; nt++) {
                int col = wn * 32 + nt * 8 + tt * 2;
                float2 rr = __half22float2(*(const __half2*)&Xb[orow + col]);
                float v0 = acc[mt][nt][hh * 2 + 0] + bb + rr.x;
                float v1 = acc[mt][nt][hh * 2 + 1] + bb + rr.y;
                *(__half2*)&Xb[orow + col] = __floats2half2_rn(v0, v1);
            }
        }
}

// ---------------- LayerNorm over channels (register-cached) ----------------
__global__ __launch_bounds__(256) void ln_kernel(const float* __restrict__ S,
                                                 const float* __restrict__ g,
                                                 const float* __restrict__ bt,
                                                 float* __restrict__ out,
                                                 int L) {
    int b = blockIdx.y;
    int l0 = blockIdx.x * 64;
    int tx = threadIdx.x & 63;
    int ty = threadIdx.x >> 6;
    const float* Sb = S + (size_t)b * NC * L + l0 + tx;
    float r[64];
    float sum = 0.f, sq = 0.f;
#pragma unroll
    for (int q = 0; q < 64; q++) {
        float v = Sb[(size_t)(ty + 4 * q) * L];
        r[q] = v;
        sum += v;
        sq = fmaf(v, v, sq);
    }
    __shared__ float ssum[4][64], ssq[4][64];
    __shared__ float smu[64], srs[64];
    ssum[ty][tx] = sum;
    ssq[ty][tx] = sq;
    __syncthreads();
    if (ty == 0) {
        float s = ssum[0][tx] + ssum[1][tx] + ssum[2][tx] + ssum[3][tx];
        float q = ssq[0][tx] + ssq[1][tx] + ssq[2][tx] + ssq[3][tx];
        float mu = s * (1.f / NC);
        float var = q * (1.f / NC) - mu * mu;
        smu[tx] = mu;
        srs[tx] = rsqrtf(var + 1e-5f);
    }
    __syncthreads();
    float* Ob = out + (size_t)b * NC * L + l0 + tx;
    float mu = smu[tx], rs = srs[tx];
#pragma unroll
    for (int q = 0; q < 64; q++) {
        int c = ty + 4 * q;
        Ob[(size_t)c * L] = (r[q] - mu) * rs * g[c] + bt[c];
    }
}

// ---------------- launch ----------------
static void* sym_addr(const void* sym) {
    void* p = nullptr;
    cudaGetSymbolAddress(&p, sym);
    return p;
}

extern "C" void kernel_launch(void* const* d_in, const int* in_sizes, int n_in,
                              void* d_out, int out_size) {
    const float* x     = (const float*)d_in[0];
    const float* ab_w1 = (const float*)d_in[1];
    const float* ab_b1 = (const float*)d_in[2];
    const float* ab_w2 = (const float*)d_in[3];
    const float* ab_b2 = (const float*)d_in[4];
    const float* db_w1 = (const float*)d_in[5];
    const float* db_b1 = (const float*)d_in[6];
    const float* db_w2 = (const float*)d_in[7];
    const float* db_b2 = (const float*)d_in[8];
    const float* ln_g  = (const float*)d_in[9];
    const float* ln_b  = (const float*)d_in[10];
    float* out = (float*)d_out;

    __half* D1 = (__half*)sym_addr(g_D1);
    __half* D2 = (__half*)sym_addr(g_D2);
    __half* D3 = (__half*)sym_addr(g_D3);
    __half* A3 = (__half*)sym_addr(g_A3);
    float*  S  = (float*) sym_addr(g_S);
    __half* Wh = (__half*)sym_addr(g_Wh);

    cudaFuncSetAttribute(resblock_all, cudaFuncAttributeMaxDynamicSharedMemorySize, RS_SMEM);
    cudaFuncSetAttribute(fused_dwt,  cudaFuncAttributeMaxDynamicSharedMemorySize, DWT_SMEM_F * 4);
    cudaFuncSetAttribute(fused_idwt, cudaFuncAttributeMaxDynamicSharedMemorySize, IDWT_SMEM_F * 4);

    const int ROWS = NB * NC;   // 4096

    convw_kernel<<<64, 256>>>(ab_w1, ab_w2, db_w1, db_w2, Wh);

    fused_dwt<<<ROWS, 512, DWT_SMEM_F * 4>>>(x, D1, D2, D3, A3);

    resblock_all<<<1024, 512, RS_SMEM>>>(D3, A3, D2, D1, Wh,
                                         ab_b1, ab_b2, db_b1, db_b2);

    fused_idwt<<<ROWS, 512, IDWT_SMEM_F * 4>>>(A3, D3, D2, D1, x, S);

    ln_kernel<<<dim3(8192 / 64, NB), 256>>>(S, ln_g, ln_b, out, 8192);
}

// round 7
// speedup vs baseline: 1.9519x; 1.1086x over previous
#include <cuda_runtime.h>
#include <cuda_fp16.h>
#include <cstdint>
#include <math.h>

#define NB 16
#define NC 256

// ---------------- scratch (device globals: no allocs allowed) ----------------
__device__ __half g_D1[NB*NC*4096];
__device__ __half g_D2[NB*NC*2048];
__device__ __half g_D3[NB*NC*1024];
__device__ __half g_A3[NB*NC*1024];
__device__ __half g_S [NB*NC*8192];
__device__ __half g_Wh[4*NC*NC];    // fp16 weights: ab_w1, ab_w2, db_w1, db_w2

// ---------------- db4 filters ----------------
__constant__ float c_dec_lo[8] = {-0.010597401785069032f, 0.0328830116668852f, 0.030841381835560764f, -0.18703481171888114f, -0.027983769416859854f, 0.6308807679298589f, 0.7148465705529157f, 0.2303778133088965f};
__constant__ float c_dec_hi[8] = {-0.2303778133088965f, 0.7148465705529157f, -0.6308807679298589f, -0.027983769416859854f, 0.18703481171888114f, 0.030841381835560764f, -0.0328830116668852f, -0.010597401785069032f};
__constant__ float c_rec_lo[8] = {0.2303778133088965f, 0.7148465705529157f, 0.6308807679298589f, -0.027983769416859854f, -0.18703481171888114f, 0.030841381835560764f, 0.0328830116668852f, -0.010597401785069032f};
__constant__ float c_rec_hi[8] = {-0.010597401785069032f, -0.0328830116668852f, 0.030841381835560764f, 0.18703481171888114f, -0.027983769416859854f, -0.6308807679298589f, 0.7148465705529157f, -0.2303778133088965f};

// ================= helpers =================
__device__ __forceinline__ uint32_t smem_u32(const void* p) {
    uint32_t a;
    asm("{ .reg .u64 t; cvta.to.shared.u64 t, %1; cvt.u32.u64 %0, t; }" : "=r"(a) : "l"(p));
    return a;
}
__device__ __forceinline__ void cp16(uint32_t dst, const void* src) {
    asm volatile("cp.async.cg.shared.global [%0], [%1], 16;" :: "r"(dst), "l"(src));
}
__device__ __forceinline__ void cp_commit() { asm volatile("cp.async.commit_group;" ::: "memory"); }
__device__ __forceinline__ void cp_wait2()  { asm volatile("cp.async.wait_group 2;" ::: "memory"); }

__device__ __forceinline__ void mma_f16(float* c, const uint32_t* a, const uint32_t* b) {
    asm volatile("mma.sync.aligned.m16n8k16.row.col.f32.f16.f16.f32 "
                 "{%0,%1,%2,%3}, {%4,%5,%6,%7}, {%8,%9}, {%0,%1,%2,%3};"
                 : "+f"(c[0]), "+f"(c[1]), "+f"(c[2]), "+f"(c[3])
                 : "r"(a[0]), "r"(a[1]), "r"(a[2]), "r"(a[3]), "r"(b[0]), "r"(b[1]));
}
__device__ __forceinline__ void ldsm4(uint32_t* r, uint32_t addr) {
    asm volatile("ldmatrix.sync.aligned.m8n8.x4.shared.b16 {%0,%1,%2,%3}, [%4];"
                 : "=r"(r[0]), "=r"(r[1]), "=r"(r[2]), "=r"(r[3]) : "r"(addr));
}
__device__ __forceinline__ void ldsm4t(uint32_t* r, uint32_t addr) {
    asm volatile("ldmatrix.sync.aligned.m8n8.x4.trans.shared.b16 {%0,%1,%2,%3}, [%4];"
                 : "=r"(r[0]), "=r"(r[1]), "=r"(r[2]), "=r"(r[3]) : "r"(addr));
}
__device__ __forceinline__ float gelu_tanh(float x) {
    const float k0 = 0.7978845608028654f;
    const float k1 = 0.044715f;
    float x3 = x * x * x;
    float t = tanhf(k0 * (x + k1 * x3));
    return 0.5f * x * (1.f + t);
}

// ---------------- convert weights to fp16 ----------------
__global__ __launch_bounds__(256) void convw_kernel(const float* __restrict__ w0,
                                                    const float* __restrict__ w1,
                                                    const float* __restrict__ w2,
                                                    const float* __restrict__ w3,
                                                    __half* __restrict__ out) {
    int i = blockIdx.x * 256 + threadIdx.x;
    const float* src[4] = {w0, w1, w2, w3};
#pragma unroll
    for (int m = 0; m < 4; m++) {
        float4 v = *(const float4*)(src[m] + i * 4);
        __half2 h0 = __floats2half2_rn(v.x, v.y);
        __half2 h1 = __floats2half2_rn(v.z, v.w);
        uint2 pk = make_uint2(*(uint32_t*)&h0, *(uint32_t*)&h1);
        *(uint2*)(out + m * 65536 + i * 4) = pk;
    }
}

// ================= fused 3-level DWT (even/odd smem split, pair-processed) =================
#define DWT_SMEM_F (2*4104 + 2*2056 + 2*1032)

__device__ __forceinline__ void dwt_level_h(const float* __restrict__ E, const float* __restrict__ O,
                                            int Lh, __half* __restrict__ dOut,
                                            float* EO, float* OO, __half* aOut) {
    for (int i = threadIdx.x; i < (Lh >> 1); i += 512) {
        int j = 2 * i;
        const float* e = E + 4 + j;
        const float* o = O + 4 + j;
        float em1 = e[-1], e0 = e[0], e1 = e[1], e2 = e[2], e3 = e[3];
        float om2 = o[-2], om1 = o[-1], o0 = o[0], o1 = o[1], o2 = o[2];
        float a0 = em1*c_dec_lo[1] + e0*c_dec_lo[3] + e1*c_dec_lo[5] + e2*c_dec_lo[7]
                 + om2*c_dec_lo[0] + om1*c_dec_lo[2] + o0*c_dec_lo[4] + o1*c_dec_lo[6];
        float a1 = e0*c_dec_lo[1] + e1*c_dec_lo[3] + e2*c_dec_lo[5] + e3*c_dec_lo[7]
                 + om1*c_dec_lo[0] + o0*c_dec_lo[2] + o1*c_dec_lo[4] + o2*c_dec_lo[6];
        float d0 = em1*c_dec_hi[1] + e0*c_dec_hi[3] + e1*c_dec_hi[5] + e2*c_dec_hi[7]
                 + om2*c_dec_hi[0] + om1*c_dec_hi[2] + o0*c_dec_hi[4] + o1*c_dec_hi[6];
        float d1 = e0*c_dec_hi[1] + e1*c_dec_hi[3] + e2*c_dec_hi[5] + e3*c_dec_hi[7]
                 + om1*c_dec_hi[0] + o0*c_dec_hi[2] + o1*c_dec_hi[4] + o2*c_dec_hi[6];
        *(__half2*)&dOut[j] = __floats2half2_rn(d0, d1);
        if (aOut) *(__half2*)&aOut[j] = __floats2half2_rn(a0, a1);
        else { EO[4 + i] = a0; OO[4 + i] = a1; }
    }
}

__global__ __launch_bounds__(512) void fused_dwt(const float* __restrict__ x,
                                                 __half* __restrict__ D1,
                                                 __half* __restrict__ D2,
                                                 __half* __restrict__ D3,
                                                 __half* __restrict__ A3) {
    extern __shared__ float sm[];
    float* E1 = sm;            // 4104
    float* O1 = sm + 4104;
    float* E2 = sm + 8208;     // 2056
    float* O2 = sm + 10264;
    float* E3 = sm + 12320;    // 1032
    float* O3 = sm + 13352;
    int row = blockIdx.x, tid = threadIdx.x;

    if (tid < 48) {            // zero pads
        int a = tid >> 3, p = tid & 7;
        float* bases[6] = {E1, O1, E2, O2, E3, O3};
        int lens[6] = {4096, 4096, 2048, 2048, 1024, 1024};
        bases[a][p < 4 ? p : lens[a] + p] = 0.f;
    }
    const float4* x4 = (const float4*)(x + (size_t)row * 8192);
    for (int i = tid; i < 2048; i += 512) {
        float4 v = x4[i];
        E1[4 + 2*i] = v.x; O1[4 + 2*i] = v.y;
        E1[5 + 2*i] = v.z; O1[5 + 2*i] = v.w;
    }
    __syncthreads();
    dwt_level_h(E1, O1, 4096, D1 + (size_t)row * 4096, E2, O2, nullptr);
    __syncthreads();
    dwt_level_h(E2, O2, 2048, D2 + (size_t)row * 2048, E3, O3, nullptr);
    __syncthreads();
    dwt_level_h(E3, O3, 1024, D3 + (size_t)row * 1024, nullptr, nullptr, A3 + (size_t)row * 1024);
}

// ================= fused 3-level IDWT + skip, fp16 out =================
// all wavelet operands staged in smem; D1 staged as fp16.
// floats: A3s 1032 | D3s 1032 | Y2 2056 | D2s 2056 | Y1 4104  = 10280
// halves: D1h 4112 (pad 8 front)  -> total 49.4 KB
#define IDWT_SMEM_B (10280*4 + 4112*2)

__global__ __launch_bounds__(512) void fused_idwt(const __half* __restrict__ A3v,
                                                  const __half* __restrict__ D3v,
                                                  const __half* __restrict__ D2v,
                                                  const __half* __restrict__ D1v,
                                                  const float* __restrict__ x,
                                                  __half* __restrict__ S) {
    extern __shared__ float sm[];
    float* A3s = sm;             // 1032
    float* D3s = sm + 1032;
    float* Y2  = sm + 2064;      // 2056
    float* D2s = sm + 4120;
    float* Y1  = sm + 6176;      // 4104
    __half* D1h = (__half*)(sm + 10280);   // 4112 halves, data at [8..4103]
    int row = blockIdx.x, tid = threadIdx.x;

    if (tid < 40) {
        int a = tid >> 3, p = tid & 7;
        float* bases[5] = {A3s, D3s, Y2, D2s, Y1};
        int lens[5] = {1024, 1024, 2048, 2048, 4096};
        bases[a][p < 4 ? p : lens[a] + p] = 0.f;
    }
    if (tid < 8) D1h[tid < 4 ? tid + 4 : tid + 4100] = __float2half(0.f);  // pads [4..7], [4104..4107]
    {
        const __half2* a3 = (const __half2*)(A3v + (size_t)row * 1024);
        const __half2* d3 = (const __half2*)(D3v + (size_t)row * 1024);
        const __half2* d2 = (const __half2*)(D2v + (size_t)row * 2048);
        const uint4*   d1 = (const uint4*)(D1v + (size_t)row * 4096);
        { float2 f = __half22float2(a3[tid]); A3s[4 + 2*tid] = f.x; A3s[5 + 2*tid] = f.y; }
        { float2 f = __half22float2(d3[tid]); D3s[4 + 2*tid] = f.x; D3s[5 + 2*tid] = f.y; }
#pragma unroll
        for (int q = 0; q < 2; q++) {
            int i = tid + q * 512;
            float2 f = __half22float2(d2[i]);
            D2s[4 + 2*i] = f.x; D2s[5 + 2*i] = f.y;
        }
        *(uint4*)&D1h[8 + 8 * tid] = d1[tid];   // 8 halves per thread, 16B aligned
    }
    __syncthreads();
    // level 3: (A3,D3) -> Y2
    for (int m = tid; m < 1024; m += 512) {
        const float* a = A3s + 4 + m;
        const float* d = D3s + 4 + m;
        float ye, yo;
        ye = a[-2]*c_rec_lo[7] + a[-1]*c_rec_lo[5] + a[0]*c_rec_lo[3] + a[1]*c_rec_lo[1]
           + d[-2]*c_rec_hi[7] + d[-1]*c_rec_hi[5] + d[0]*c_rec_hi[3] + d[1]*c_rec_hi[1];
        yo = a[-1]*c_rec_lo[6] + a[0]*c_rec_lo[4] + a[1]*c_rec_lo[2] + a[2]*c_rec_lo[0]
           + d[-1]*c_rec_hi[6] + d[0]*c_rec_hi[4] + d[1]*c_rec_hi[2] + d[2]*c_rec_hi[0];
        Y2[4 + 2*m] = ye;
        Y2[5 + 2*m] = yo;
    }
    __syncthreads();
    // level 2: (Y2,D2) -> Y1
    for (int m = tid; m < 2048; m += 512) {
        const float* a = Y2 + 4 + m;
        const float* d = D2s + 4 + m;
        float ye, yo;
        ye = a[-2]*c_rec_lo[7] + a[-1]*c_rec_lo[5] + a[0]*c_rec_lo[3] + a[1]*c_rec_lo[1]
           + d[-2]*c_rec_hi[7] + d[-1]*c_rec_hi[5] + d[0]*c_rec_hi[3] + d[1]*c_rec_hi[1];
        yo = a[-1]*c_rec_lo[6] + a[0]*c_rec_lo[4] + a[1]*c_rec_lo[2] + a[2]*c_rec_lo[0]
           + d[-1]*c_rec_hi[6] + d[0]*c_rec_hi[4] + d[1]*c_rec_hi[2] + d[2]*c_rec_hi[0];
        Y1[4 + 2*m] = ye;
        Y1[5 + 2*m] = yo;
    }
    __syncthreads();
    // level 1 + skip -> S (fp16)
    const float* xr = x + (size_t)row * 8192;
    __half2* Sr = (__half2*)(S + (size_t)row * 8192);
    for (int m = tid; m < 4096; m += 512) {
        const float* a = Y1 + 4 + m;
        const __half* dh = D1h + 8 + m;
        float dm2 = __half2float(dh[-2]), dm1 = __half2float(dh[-1]), d0 = __half2float(dh[0]);
        float dp1 = __half2float(dh[1]),  dp2 = __half2float(dh[2]);
        float ye, yo;
        ye = a[-2]*c_rec_lo[7] + a[-1]*c_rec_lo[5] + a[0]*c_rec_lo[3] + a[1]*c_rec_lo[1]
           + dm2*c_rec_hi[7] + dm1*c_rec_hi[5] + d0*c_rec_hi[3] + dp1*c_rec_hi[1];
        yo = a[-1]*c_rec_lo[6] + a[0]*c_rec_lo[4] + a[1]*c_rec_lo[2] + a[2]*c_rec_lo[0]
           + dm1*c_rec_hi[6] + d0*c_rec_hi[4] + dp1*c_rec_hi[2] + dp2*c_rec_hi[0];
        float2 xv = *(const float2*)&xr[2*m];
        Sr[m] = __floats2half2_rn(ye + xv.x, yo + xv.y);
    }
}

// ================= combined fused res blocks, fp16 mma, fp16 activations =================
#define A_STAGE_B (256*80)      // 20480
#define B_STAGE_B (32*272)      // 8704
#define H_BYTES   (256*272)     // 69632
#define RS_SMEM   (4*A_STAGE_B + 4*B_STAGE_B + H_BYTES)   // 186368

__global__ __launch_bounds__(512, 1) void resblock_all(
        __half* __restrict__ D3, __half* __restrict__ A3,
        __half* __restrict__ D2, __half* __restrict__ D1,
        const __half* __restrict__ Wh,
        const float* __restrict__ ab_b1, const float* __restrict__ ab_b2,
        const float* __restrict__ db_b1, const float* __restrict__ db_b2) {
    extern __shared__ char smem[];
    uint32_t sA = smem_u32(smem);
    uint32_t sB = sA + 4 * A_STAGE_B;
    uint32_t sH = sB + 4 * B_STAGE_B;

    int tid = threadIdx.x;
    int wid = tid >> 5, lane = tid & 31;
    int wm = wid >> 2, wn = wid & 3;
    int g = lane >> 2, tt = lane & 3;
    int l15 = lane & 15, lhi = (lane >> 4) << 4;

    int id = blockIdx.x;
    int b = id >> 6, slot = id & 63;
    __half* X; int L, ln;
    const __half *W1, *W2; const float *b1, *b2;
    if (slot < 8)       { X = D3; L = 1024; ln = slot * 128;        W1 = Wh + 2*65536; W2 = Wh + 3*65536; b1 = db_b1; b2 = db_b2; }
    else if (slot < 16) { X = A3; L = 1024; ln = (slot - 8) * 128;  W1 = Wh + 0*65536; W2 = Wh + 1*65536; b1 = ab_b1; b2 = ab_b2; }
    else if (slot < 32) { X = D2; L = 2048; ln = (slot - 16) * 128; W1 = Wh + 2*65536; W2 = Wh + 3*65536; b1 = db_b1; b2 = db_b2; }
    else                { X = D1; L = 4096; ln = (slot - 32) * 128; W1 = Wh + 2*65536; W2 = Wh + 3*65536; b1 = db_b1; b2 = db_b2; }
    __half* Xb = X + (size_t)b * NC * L + ln;

    float acc[4][4][4];
#pragma unroll
    for (int mt = 0; mt < 4; mt++)
#pragma unroll
        for (int nt = 0; nt < 4; nt++)
#pragma unroll
            for (int r = 0; r < 4; r++) acc[mt][nt][r] = 0.f;

    auto loadAB = [&](int c, int s) {
        const __half* wsrc = (c < 8 ? W1 : W2) + (c & 7) * 32;
#pragma unroll
        for (int q = 0; q < 2; q++) {
            int idx = tid + q * 512;
            int r = idx >> 2, u = idx & 3;
            cp16(sA + s * A_STAGE_B + r * 80 + u * 16, wsrc + r * 256 + u * 8);
        }
        if (c < 8) {
            int k = tid >> 4, u = tid & 15;
            cp16(sB + s * B_STAGE_B + k * 272 + u * 16,
                 Xb + (size_t)(c * 32 + k) * L + u * 8);
        }
    };
    auto compute = [&](int c, int s) {
        uint32_t Abase = sA + s * A_STAGE_B + (wm * 64) * 80;
        uint32_t Bbase = (c < 8) ? (sB + s * B_STAGE_B) : (sH + (uint32_t)(c - 8) * 32 * 272);
#pragma unroll
        for (int kk = 0; kk < 2; kk++) {
            uint32_t a[4][4];
#pragma unroll
            for (int mt = 0; mt < 4; mt++)
                ldsm4(a[mt], Abase + (mt * 16 + l15) * 80 + kk * 32 + lhi);
            uint32_t bf[2][4];
#pragma unroll
            for (int p = 0; p < 2; p++)
                ldsm4t(bf[p], Bbase + (kk * 16 + l15) * 272 + (wn * 32 + p * 16) * 2 + lhi);
#pragma unroll
            for (int mt = 0; mt < 4; mt++)
#pragma unroll
                for (int nt = 0; nt < 4; nt++)
                    mma_f16(acc[mt][nt], a[mt], &bf[nt >> 1][(nt & 1) * 2]);
        }
    };

    loadAB(0, 0); cp_commit();
    loadAB(1, 1); cp_commit();
    loadAB(2, 2); cp_commit();

#pragma unroll 1
    for (int c = 0; c < 16; c++) {
        int s = c & 3;
        cp_wait2();
        __syncthreads();
        if (c + 3 < 16) loadAB(c + 3, (c + 3) & 3);
        cp_commit();
        compute(c, s);
        if (c == 7) {
#pragma unroll
            for (int mt = 0; mt < 4; mt++)
#pragma unroll
                for (int hh = 0; hh < 2; hh++) {
                    int m = wm * 64 + mt * 16 + g + hh * 8;
                    float bb = b1[m];
#pragma unroll
                    for (int nt = 0; nt < 4; nt++) {
                        float v0 = gelu_tanh(acc[mt][nt][hh * 2 + 0] + bb);
                        float v1 = gelu_tanh(acc[mt][nt][hh * 2 + 1] + bb);
                        __half2 h = __floats2half2_rn(v0, v1);
                        asm volatile("st.shared.b32 [%0], %1;"
                                     :: "r"(sH + m * 272 + (wn * 32 + nt * 8 + tt * 2) * 2),
                                        "r"(*(uint32_t*)&h));
                        acc[mt][nt][hh * 2 + 0] = 0.f;
                        acc[mt][nt][hh * 2 + 1] = 0.f;
                    }
                }
        }
    }

#pragma unroll
    for (int mt = 0; mt < 4; mt++)
#pragma unroll
        for (int hh = 0; hh < 2; hh++) {
            int m = wm * 64 + mt * 16 + g + hh * 8;
            float bb = b2[m];
            size_t orow = (size_t)m * L;
#pragma unroll
            for (int nt = 0; nt < 4; nt++) {
                int col = wn * 32 + nt * 8 + tt * 2;
                float2 rr = __half22float2(*(const __half2*)&Xb[orow + col]);
                float v0 = acc[mt][nt][hh * 2 + 0] + bb + rr.x;
                float v1 = acc[mt][nt][hh * 2 + 1] + bb + rr.y;
                *(__half2*)&Xb[orow + col] = __floats2half2_rn(v0, v1);
            }
        }
}

// ---------------- LayerNorm over channels: fp16 in, fp32 out ----------------
// CTA covers 128 l-positions: tx (0..63) owns two adjacent l (half2), ty strides channels.
__global__ __launch_bounds__(256) void ln_kernel(const __half* __restrict__ S,
                                                 const float* __restrict__ g,
                                                 const float* __restrict__ bt,
                                                 float* __restrict__ out) {
    int b = blockIdx.y;
    int l0 = blockIdx.x * 128;
    int tx = threadIdx.x & 63;
    int ty = threadIdx.x >> 6;     // 0..3
    const __half2* Sb = (const __half2*)S;
    uint32_t r[64];
    float s0 = 0.f, s1 = 0.f, q0 = 0.f, q1 = 0.f;
#pragma unroll
    for (int q = 0; q < 64; q++) {
        int c = ty + 4 * q;
        __half2 h = Sb[(size_t)(b * NC + c) * 4096 + (l0 >> 1) + tx];
        r[q] = *(uint32_t*)&h;
        float2 f = __half22float2(h);
        s0 += f.x; s1 += f.y;
        q0 = fmaf(f.x, f.x, q0);
        q1 = fmaf(f.y, f.y, q1);
    }
    __shared__ float2 ssum[4][64], ssq[4][64];
    __shared__ float2 smu[64], srs[64];
    ssum[ty][tx] = make_float2(s0, s1);
    ssq[ty][tx] = make_float2(q0, q1);
    __syncthreads();
    if (ty == 0) {
        float2 s = ssum[0][tx], q = ssq[0][tx];
#pragma unroll
        for (int t = 1; t < 4; t++) {
            s.x += ssum[t][tx].x; s.y += ssum[t][tx].y;
            q.x += ssq[t][tx].x;  q.y += ssq[t][tx].y;
        }
        float mu0 = s.x * (1.f / NC), mu1 = s.y * (1.f / NC);
        float v0 = q.x * (1.f / NC) - mu0 * mu0;
        float v1 = q.y * (1.f / NC) - mu1 * mu1;
        smu[tx] = make_float2(mu0, mu1);
        srs[tx] = make_float2(rsqrtf(v0 + 1e-5f), rsqrtf(v1 + 1e-5f));
    }
    __syncthreads();
    float2 mu = smu[tx], rs = srs[tx];
#pragma unroll
    for (int q = 0; q < 64; q++) {
        int c = ty + 4 * q;
        __half2 h = *(__half2*)&r[q];
        float2 f = __half22float2(h);
        float gg = g[c], bbv = bt[c];
        float o0 = (f.x - mu.x) * rs.x * gg + bbv;
        float o1 = (f.y - mu.y) * rs.y * gg + bbv;
        *(float2*)&out[(size_t)(b * NC + c) * 8192 + l0 + 2 * tx] = make_float2(o0, o1);
    }
}

// ---------------- launch ----------------
static void* sym_addr(const void* sym) {
    void* p = nullptr;
    cudaGetSymbolAddress(&p, sym);
    return p;
}

extern "C" void kernel_launch(void* const* d_in, const int* in_sizes, int n_in,
                              void* d_out, int out_size) {
    const float* x     = (const float*)d_in[0];
    const float* ab_w1 = (const float*)d_in[1];
    const float* ab_b1 = (const float*)d_in[2];
    const float* ab_w2 = (const float*)d_in[3];
    const float* ab_b2 = (const float*)d_in[4];
    const float* db_w1 = (const float*)d_in[5];
    const float* db_b1 = (const float*)d_in[6];
    const float* db_w2 = (const float*)d_in[7];
    const float* db_b2 = (const float*)d_in[8];
    const float* ln_g  = (const float*)d_in[9];
    const float* ln_b  = (const float*)d_in[10];
    float* out = (float*)d_out;

    __half* D1 = (__half*)sym_addr(g_D1);
    __half* D2 = (__half*)sym_addr(g_D2);
    __half* D3 = (__half*)sym_addr(g_D3);
    __half* A3 = (__half*)sym_addr(g_A3);
    __half* S  = (__half*)sym_addr(g_S);
    __half* Wh = (__half*)sym_addr(g_Wh);

    cudaFuncSetAttribute(resblock_all, cudaFuncAttributeMaxDynamicSharedMemorySize, RS_SMEM);
    cudaFuncSetAttribute(fused_dwt,  cudaFuncAttributeMaxDynamicSharedMemorySize, DWT_SMEM_F * 4);
    cudaFuncSetAttribute(fused_idwt, cudaFuncAttributeMaxDynamicSharedMemorySize, IDWT_SMEM_B);

    const int ROWS = NB * NC;   // 4096

    convw_kernel<<<64, 256>>>(ab_w1, ab_w2, db_w1, db_w2, Wh);

    fused_dwt<<<ROWS, 512, DWT_SMEM_F * 4>>>(x, D1, D2, D3, A3);

    resblock_all<<<1024, 512, RS_SMEM>>>(D3, A3, D2, D1, Wh,
                                         ab_b1, ab_b2, db_b1, db_b2);

    fused_idwt<<<ROWS, 512, IDWT_SMEM_B>>>(A3, D3, D2, D1, x, S);

    ln_kernel<<<dim3(8192 / 128, NB), 256>>>(S, ln_g, ln_b, out);
}

// round 8
// speedup vs baseline: 2.2775x; 1.1668x over previous
#include <cuda_runtime.h>
#include <cuda_fp16.h>
#include <cstdint>
#include <math.h>

#define NB 16
#define NC 256

// ---------------- scratch (device globals: no allocs allowed) ----------------
__device__ __half g_D1[NB*NC*4096];
__device__ __half g_D2[NB*NC*2048];
__device__ __half g_D3[NB*NC*1024];
__device__ __half g_A3[NB*NC*1024];
__device__ __half g_S [NB*NC*8192];
__device__ __half g_Wh[4*NC*NC];    // fp16 weights: ab_w1, ab_w2, db_w1, db_w2

// ---------------- db4 filters ----------------
__constant__ float c_dec_lo[8] = {-0.010597401785069032f, 0.0328830116668852f, 0.030841381835560764f, -0.18703481171888114f, -0.027983769416859854f, 0.6308807679298589f, 0.7148465705529157f, 0.2303778133088965f};
__constant__ float c_dec_hi[8] = {-0.2303778133088965f, 0.7148465705529157f, -0.6308807679298589f, -0.027983769416859854f, 0.18703481171888114f, 0.030841381835560764f, -0.0328830116668852f, -0.010597401785069032f};
__constant__ float c_rec_lo[8] = {0.2303778133088965f, 0.7148465705529157f, 0.6308807679298589f, -0.027983769416859854f, -0.18703481171888114f, 0.030841381835560764f, 0.0328830116668852f, -0.010597401785069032f};
__constant__ float c_rec_hi[8] = {-0.010597401785069032f, -0.0328830116668852f, 0.030841381835560764f, 0.18703481171888114f, -0.027983769416859854f, -0.6308807679298589f, 0.7148465705529157f, -0.2303778133088965f};

// ================= helpers =================
__device__ __forceinline__ uint32_t smem_u32(const void* p) {
    uint32_t a;
    asm("{ .reg .u64 t; cvta.to.shared.u64 t, %1; cvt.u32.u64 %0, t; }" : "=r"(a) : "l"(p));
    return a;
}
__device__ __forceinline__ void cp16(uint32_t dst, const void* src) {
    asm volatile("cp.async.cg.shared.global [%0], [%1], 16;" :: "r"(dst), "l"(src));
}
__device__ __forceinline__ void cp_commit() { asm volatile("cp.async.commit_group;" ::: "memory"); }
__device__ __forceinline__ void cp_wait2()  { asm volatile("cp.async.wait_group 2;" ::: "memory"); }

__device__ __forceinline__ void mma_f16(float* c, const uint32_t* a, const uint32_t* b) {
    asm volatile("mma.sync.aligned.m16n8k16.row.col.f32.f16.f16.f32 "
                 "{%0,%1,%2,%3}, {%4,%5,%6,%7}, {%8,%9}, {%0,%1,%2,%3};"
                 : "+f"(c[0]), "+f"(c[1]), "+f"(c[2]), "+f"(c[3])
                 : "r"(a[0]), "r"(a[1]), "r"(a[2]), "r"(a[3]), "r"(b[0]), "r"(b[1]));
}
__device__ __forceinline__ void ldsm4(uint32_t* r, uint32_t addr) {
    asm volatile("ldmatrix.sync.aligned.m8n8.x4.shared.b16 {%0,%1,%2,%3}, [%4];"
                 : "=r"(r[0]), "=r"(r[1]), "=r"(r[2]), "=r"(r[3]) : "r"(addr));
}
__device__ __forceinline__ void ldsm4t(uint32_t* r, uint32_t addr) {
    asm volatile("ldmatrix.sync.aligned.m8n8.x4.trans.shared.b16 {%0,%1,%2,%3}, [%4];"
                 : "=r"(r[0]), "=r"(r[1]), "=r"(r[2]), "=r"(r[3]) : "r"(addr));
}
__device__ __forceinline__ float gelu_tanh(float x) {
    const float k0 = 0.7978845608028654f;
    const float k1 = 0.044715f;
    float x3 = x * x * x;
    float t = tanhf(k0 * (x + k1 * x3));
    return 0.5f * x * (1.f + t);
}

// ---------------- convert weights to fp16 ----------------
__global__ __launch_bounds__(256) void convw_kernel(const float* __restrict__ w0,
                                                    const float* __restrict__ w1,
                                                    const float* __restrict__ w2,
                                                    const float* __restrict__ w3,
                                                    __half* __restrict__ out) {
    int i = blockIdx.x * 256 + threadIdx.x;
    const float* src[4] = {w0, w1, w2, w3};
#pragma unroll
    for (int m = 0; m < 4; m++) {
        float4 v = *(const float4*)(src[m] + i * 4);
        __half2 h0 = __floats2half2_rn(v.x, v.y);
        __half2 h1 = __floats2half2_rn(v.z, v.w);
        uint2 pk = make_uint2(*(uint32_t*)&h0, *(uint32_t*)&h1);
        *(uint2*)(out + m * 65536 + i * 4) = pk;
    }
}

// ================= fused 3-level DWT (even/odd smem split, pair-processed) =================
#define DWT_SMEM_F (2*4104 + 2*2056 + 2*1032)

__device__ __forceinline__ void dwt_level_h(const float* __restrict__ E, const float* __restrict__ O,
                                            int Lh, __half* __restrict__ dOut,
                                            float* EO, float* OO, __half* aOut) {
    for (int i = threadIdx.x; i < (Lh >> 1); i += 512) {
        int j = 2 * i;
        const float* e = E + 4 + j;
        const float* o = O + 4 + j;
        float em1 = e[-1], e0 = e[0], e1 = e[1], e2 = e[2], e3 = e[3];
        float om2 = o[-2], om1 = o[-1], o0 = o[0], o1 = o[1], o2 = o[2];
        float a0 = em1*c_dec_lo[1] + e0*c_dec_lo[3] + e1*c_dec_lo[5] + e2*c_dec_lo[7]
                 + om2*c_dec_lo[0] + om1*c_dec_lo[2] + o0*c_dec_lo[4] + o1*c_dec_lo[6];
        float a1 = e0*c_dec_lo[1] + e1*c_dec_lo[3] + e2*c_dec_lo[5] + e3*c_dec_lo[7]
                 + om1*c_dec_lo[0] + o0*c_dec_lo[2] + o1*c_dec_lo[4] + o2*c_dec_lo[6];
        float d0 = em1*c_dec_hi[1] + e0*c_dec_hi[3] + e1*c_dec_hi[5] + e2*c_dec_hi[7]
                 + om2*c_dec_hi[0] + om1*c_dec_hi[2] + o0*c_dec_hi[4] + o1*c_dec_hi[6];
        float d1 = e0*c_dec_hi[1] + e1*c_dec_hi[3] + e2*c_dec_hi[5] + e3*c_dec_hi[7]
                 + om1*c_dec_hi[0] + o0*c_dec_hi[2] + o1*c_dec_hi[4] + o2*c_dec_hi[6];
        *(__half2*)&dOut[j] = __floats2half2_rn(d0, d1);
        if (aOut) *(__half2*)&aOut[j] = __floats2half2_rn(a0, a1);
        else { EO[4 + i] = a0; OO[4 + i] = a1; }
    }
}

__global__ __launch_bounds__(512) void fused_dwt(const float* __restrict__ x,
                                                 __half* __restrict__ D1,
                                                 __half* __restrict__ D2,
                                                 __half* __restrict__ D3,
                                                 __half* __restrict__ A3) {
    extern __shared__ float sm[];
    float* E1 = sm;            // 4104
    float* O1 = sm + 4104;
    float* E2 = sm + 8208;     // 2056
    float* O2 = sm + 10264;
    float* E3 = sm + 12320;    // 1032
    float* O3 = sm + 13352;
    int row = blockIdx.x, tid = threadIdx.x;

    if (tid < 48) {            // zero pads
        int a = tid >> 3, p = tid & 7;
        float* bases[6] = {E1, O1, E2, O2, E3, O3};
        int lens[6] = {4096, 4096, 2048, 2048, 1024, 1024};
        bases[a][p < 4 ? p : lens[a] + p] = 0.f;
    }
    const float4* x4 = (const float4*)(x + (size_t)row * 8192);
    for (int i = tid; i < 2048; i += 512) {
        float4 v = x4[i];
        *(float2*)&E1[4 + 2*i] = make_float2(v.x, v.z);
        *(float2*)&O1[4 + 2*i] = make_float2(v.y, v.w);
    }
    __syncthreads();
    dwt_level_h(E1, O1, 4096, D1 + (size_t)row * 4096, E2, O2, nullptr);
    __syncthreads();
    dwt_level_h(E2, O2, 2048, D2 + (size_t)row * 2048, E3, O3, nullptr);
    __syncthreads();
    dwt_level_h(E3, O3, 1024, D3 + (size_t)row * 1024, nullptr, nullptr, A3 + (size_t)row * 1024);
}

// ================= fused 3-level IDWT + skip, quad-processed, conflict-free =================
// half arrays: front pad 8, back pad 8 (16B-aligned bulk stores); float arrays pad 4/4.
// A3h 1040h | D3h 1040h | D2h 2064h | D1h 4112h | Y2 2056f | Y1 4104f
#define IDWT_A3H 0
#define IDWT_D3H 2080
#define IDWT_D2H 4160
#define IDWT_D1H 8288
#define IDWT_Y2  16512
#define IDWT_Y1  24736
#define IDWT_SMEM_B 41152

__global__ __launch_bounds__(512) void fused_idwt(const __half* __restrict__ A3v,
                                                  const __half* __restrict__ D3v,
                                                  const __half* __restrict__ D2v,
                                                  const __half* __restrict__ D1v,
                                                  const float* __restrict__ x,
                                                  __half* __restrict__ S) {
    extern __shared__ char smc[];
    __half* A3h = (__half*)(smc + IDWT_A3H);
    __half* D3h = (__half*)(smc + IDWT_D3H);
    __half* D2h = (__half*)(smc + IDWT_D2H);
    __half* D1h = (__half*)(smc + IDWT_D1H);
    float*  Y2  = (float*)(smc + IDWT_Y2);
    float*  Y1  = (float*)(smc + IDWT_Y1);
    int row = blockIdx.x, tid = threadIdx.x;

    // zero pads
    if (tid < 8) {
        __half* hb[4] = {A3h, D3h, D2h, D1h};
        int hl[4] = {1024, 1024, 2048, 4096};
        int a = tid >> 1, e = tid & 1;
        uint4 z = make_uint4(0, 0, 0, 0);
        *(uint4*)&hb[a][e ? 8 + hl[a] : 0] = z;
    } else if (tid < 12) {
        float* fb[2] = {Y2, Y1};
        int fl[2] = {2048, 4096};
        int a = (tid - 8) >> 1, e = tid & 1;
        *(float4*)&fb[a][e ? 4 + fl[a] : 0] = make_float4(0.f, 0.f, 0.f, 0.f);
    }
    // stage coefficients (16B bulk, fp16)
    {
        const uint4* a3 = (const uint4*)(A3v + (size_t)row * 1024);   // 128
        const uint4* d3 = (const uint4*)(D3v + (size_t)row * 1024);   // 128
        const uint4* d2 = (const uint4*)(D2v + (size_t)row * 2048);   // 256
        const uint4* d1 = (const uint4*)(D1v + (size_t)row * 4096);   // 512
        if (tid < 128)       *(uint4*)&A3h[8 + 8 * tid] = a3[tid];
        else if (tid < 256)  *(uint4*)&D3h[8 + 8 * (tid - 128)] = d3[tid - 128];
        else                 *(uint4*)&D2h[8 + 8 * (tid - 256)] = d2[tid - 256];
        *(uint4*)&D1h[8 + 8 * tid] = d1[tid];
    }
    __syncthreads();

    // ---- level 3: (A3h, D3h fp16) -> Y2 (quad per thread) ----
    {
        int i = tid;   // 512 pairs exactly
        float2 am = __half22float2(*(const __half2*)&A3h[6 + 2*i]);
        float2 ac = __half22float2(*(const __half2*)&A3h[8 + 2*i]);
        float2 ap = __half22float2(*(const __half2*)&A3h[10 + 2*i]);
        float2 dm = __half22float2(*(const __half2*)&D3h[6 + 2*i]);
        float2 dc = __half22float2(*(const __half2*)&D3h[8 + 2*i]);
        float2 dp = __half22float2(*(const __half2*)&D3h[10 + 2*i]);
        float y0 = am.x*c_rec_lo[7] + am.y*c_rec_lo[5] + ac.x*c_rec_lo[3] + ac.y*c_rec_lo[1]
                 + dm.x*c_rec_hi[7] + dm.y*c_rec_hi[5] + dc.x*c_rec_hi[3] + dc.y*c_rec_hi[1];
        float y1 = am.y*c_rec_lo[6] + ac.x*c_rec_lo[4] + ac.y*c_rec_lo[2] + ap.x*c_rec_lo[0]
                 + dm.y*c_rec_hi[6] + dc.x*c_rec_hi[4] + dc.y*c_rec_hi[2] + dp.x*c_rec_hi[0];
        float y2 = am.y*c_rec_lo[7] + ac.x*c_rec_lo[5] + ac.y*c_rec_lo[3] + ap.x*c_rec_lo[1]
                 + dm.y*c_rec_hi[7] + dc.x*c_rec_hi[5] + dc.y*c_rec_hi[3] + dp.x*c_rec_hi[1];
        float y3 = ac.x*c_rec_lo[6] + ac.y*c_rec_lo[4] + ap.x*c_rec_lo[2] + ap.y*c_rec_lo[0]
                 + dc.x*c_rec_hi[6] + dc.y*c_rec_hi[4] + dp.x*c_rec_hi[2] + dp.y*c_rec_hi[0];
        *(float4*)&Y2[4 + 4*i] = make_float4(y0, y1, y2, y3);
    }
    __syncthreads();

    // ---- level 2: (Y2 fp32, D2h fp16) -> Y1 ----
#pragma unroll
    for (int q = 0; q < 2; q++) {
        int i = tid + q * 512;
        float2 am = *(const float2*)&Y2[2 + 2*i];
        float2 ac = *(const float2*)&Y2[4 + 2*i];
        float2 ap = *(const float2*)&Y2[6 + 2*i];
        float2 dm = __half22float2(*(const __half2*)&D2h[6 + 2*i]);
        float2 dc = __half22float2(*(const __half2*)&D2h[8 + 2*i]);
        float2 dp = __half22float2(*(const __half2*)&D2h[10 + 2*i]);
        float y0 = am.x*c_rec_lo[7] + am.y*c_rec_lo[5] + ac.x*c_rec_lo[3] + ac.y*c_rec_lo[1]
                 + dm.x*c_rec_hi[7] + dm.y*c_rec_hi[5] + dc.x*c_rec_hi[3] + dc.y*c_rec_hi[1];
        float y1 = am.y*c_rec_lo[6] + ac.x*c_rec_lo[4] + ac.y*c_rec_lo[2] + ap.x*c_rec_lo[0]
                 + dm.y*c_rec_hi[6] + dc.x*c_rec_hi[4] + dc.y*c_rec_hi[2] + dp.x*c_rec_hi[0];
        float y2 = am.y*c_rec_lo[7] + ac.x*c_rec_lo[5] + ac.y*c_rec_lo[3] + ap.x*c_rec_lo[1]
                 + dm.y*c_rec_hi[7] + dc.x*c_rec_hi[5] + dc.y*c_rec_hi[3] + dp.x*c_rec_hi[1];
        float y3 = ac.x*c_rec_lo[6] + ac.y*c_rec_lo[4] + ap.x*c_rec_lo[2] + ap.y*c_rec_lo[0]
                 + dc.x*c_rec_hi[6] + dc.y*c_rec_hi[4] + dp.x*c_rec_hi[2] + dp.y*c_rec_hi[0];
        *(float4*)&Y1[4 + 4*i] = make_float4(y0, y1, y2, y3);
    }
    __syncthreads();

    // ---- level 1 + skip -> S (fp16) ----
    const float* xr = x + (size_t)row * 8192;
    __half* Sr = S + (size_t)row * 8192;
#pragma unroll
    for (int q = 0; q < 4; q++) {
        int i = tid + q * 512;
        float2 am = *(const float2*)&Y1[2 + 2*i];
        float2 ac = *(const float2*)&Y1[4 + 2*i];
        float2 ap = *(const float2*)&Y1[6 + 2*i];
        float2 dm = __half22float2(*(const __half2*)&D1h[6 + 2*i]);
        float2 dc = __half22float2(*(const __half2*)&D1h[8 + 2*i]);
        float2 dp = __half22float2(*(const __half2*)&D1h[10 + 2*i]);
        float y0 = am.x*c_rec_lo[7] + am.y*c_rec_lo[5] + ac.x*c_rec_lo[3] + ac.y*c_rec_lo[1]
                 + dm.x*c_rec_hi[7] + dm.y*c_rec_hi[5] + dc.x*c_rec_hi[3] + dc.y*c_rec_hi[1];
        float y1 = am.y*c_rec_lo[6] + ac.x*c_rec_lo[4] + ac.y*c_rec_lo[2] + ap.x*c_rec_lo[0]
                 + dm.y*c_rec_hi[6] + dc.x*c_rec_hi[4] + dc.y*c_rec_hi[2] + dp.x*c_rec_hi[0];
        float y2 = am.y*c_rec_lo[7] + ac.x*c_rec_lo[5] + ac.y*c_rec_lo[3] + ap.x*c_rec_lo[1]
                 + dm.y*c_rec_hi[7] + dc.x*c_rec_hi[5] + dc.y*c_rec_hi[3] + dp.x*c_rec_hi[1];
        float y3 = ac.x*c_rec_lo[6] + ac.y*c_rec_lo[4] + ap.x*c_rec_lo[2] + ap.y*c_rec_lo[0]
                 + dc.x*c_rec_hi[6] + dc.y*c_rec_hi[4] + dp.x*c_rec_hi[2] + dp.y*c_rec_hi[0];
        float4 xv = *(const float4*)&xr[4*i];
        __half2 h0 = __floats2half2_rn(y0 + xv.x, y1 + xv.y);
        __half2 h1 = __floats2half2_rn(y2 + xv.z, y3 + xv.w);
        uint2 pk = make_uint2(*(uint32_t*)&h0, *(uint32_t*)&h1);
        *(uint2*)&Sr[4*i] = pk;
    }
}

// ================= combined fused res blocks, fp16 mma, X-resident =================
// A: 4-stage ring (20480B each). B: 8 dedicated stages (X stays resident -> smem residual read).
// H: fp16 [256 k][128 n] pitch 272B.
#define A_STAGE_B (256*80)      // 20480
#define B_STAGE_B (32*272)      // 8704
#define H_BYTES   (256*272)     // 69632
#define RS_SMEM   (4*A_STAGE_B + 8*B_STAGE_B + H_BYTES)   // 221184

__global__ __launch_bounds__(512, 1) void resblock_all(
        __half* __restrict__ D3, __half* __restrict__ A3,
        __half* __restrict__ D2, __half* __restrict__ D1,
        const __half* __restrict__ Wh,
        const float* __restrict__ ab_b1, const float* __restrict__ ab_b2,
        const float* __restrict__ db_b1, const float* __restrict__ db_b2) {
    extern __shared__ char smem[];
    uint32_t sA = smem_u32(smem);
    uint32_t sB = sA + 4 * A_STAGE_B;
    uint32_t sH = sB + 8 * B_STAGE_B;

    int tid = threadIdx.x;
    int wid = tid >> 5, lane = tid & 31;
    int wm = wid >> 2, wn = wid & 3;
    int g = lane >> 2, tt = lane & 3;
    int l15 = lane & 15, lhi = (lane >> 4) << 4;

    int id = blockIdx.x;
    int b = id >> 6, slot = id & 63;
    __half* X; int L, ln;
    const __half *W1, *W2; const float *b1, *b2;
    if (slot < 8)       { X = D3; L = 1024; ln = slot * 128;        W1 = Wh + 2*65536; W2 = Wh + 3*65536; b1 = db_b1; b2 = db_b2; }
    else if (slot < 16) { X = A3; L = 1024; ln = (slot - 8) * 128;  W1 = Wh + 0*65536; W2 = Wh + 1*65536; b1 = ab_b1; b2 = ab_b2; }
    else if (slot < 32) { X = D2; L = 2048; ln = (slot - 16) * 128; W1 = Wh + 2*65536; W2 = Wh + 3*65536; b1 = db_b1; b2 = db_b2; }
    else                { X = D1; L = 4096; ln = (slot - 32) * 128; W1 = Wh + 2*65536; W2 = Wh + 3*65536; b1 = db_b1; b2 = db_b2; }
    __half* Xb = X + (size_t)b * NC * L + ln;

    float acc[4][4][4];
#pragma unroll
    for (int mt = 0; mt < 4; mt++)
#pragma unroll
        for (int nt = 0; nt < 4; nt++)
#pragma unroll
            for (int r = 0; r < 4; r++) acc[mt][nt][r] = 0.f;

    auto loadAB = [&](int c, int s) {
        const __half* wsrc = (c < 8 ? W1 : W2) + (c & 7) * 32;
#pragma unroll
        for (int q = 0; q < 2; q++) {
            int idx = tid + q * 512;
            int r = idx >> 2, u = idx & 3;
            cp16(sA + s * A_STAGE_B + r * 80 + u * 16, wsrc + r * 256 + u * 8);
        }
        if (c < 8) {   // B: dedicated stage = c (X stays resident)
            int k = tid >> 4, u = tid & 15;
            cp16(sB + c * B_STAGE_B + k * 272 + u * 16,
                 Xb + (size_t)(c * 32 + k) * L + u * 8);
        }
    };
    auto compute = [&](int c, int s) {
        uint32_t Abase = sA + s * A_STAGE_B + (wm * 64) * 80;
        uint32_t Bbase = (c < 8) ? (sB + (uint32_t)c * B_STAGE_B)
                                 : (sH + (uint32_t)(c - 8) * 32 * 272);
#pragma unroll
        for (int kk = 0; kk < 2; kk++) {
            uint32_t a[4][4];
#pragma unroll
            for (int mt = 0; mt < 4; mt++)
                ldsm4(a[mt], Abase + (mt * 16 + l15) * 80 + kk * 32 + lhi);
            uint32_t bf[2][4];
#pragma unroll
            for (int p = 0; p < 2; p++)
                ldsm4t(bf[p], Bbase + (kk * 16 + l15) * 272 + (wn * 32 + p * 16) * 2 + lhi);
#pragma unroll
            for (int mt = 0; mt < 4; mt++)
#pragma unroll
                for (int nt = 0; nt < 4; nt++)
                    mma_f16(acc[mt][nt], a[mt], &bf[nt >> 1][(nt & 1) * 2]);
        }
    };

    loadAB(0, 0); cp_commit();
    loadAB(1, 1); cp_commit();
    loadAB(2, 2); cp_commit();

#pragma unroll 1
    for (int c = 0; c < 16; c++) {
        int s = c & 3;
        cp_wait2();
        __syncthreads();
        if (c + 3 < 16) loadAB(c + 3, (c + 3) & 3);
        cp_commit();
        compute(c, s);
        if (c == 7) {
#pragma unroll
            for (int mt = 0; mt < 4; mt++)
#pragma unroll
                for (int hh = 0; hh < 2; hh++) {
                    int m = wm * 64 + mt * 16 + g + hh * 8;
                    float bb = b1[m];
#pragma unroll
                    for (int nt = 0; nt < 4; nt++) {
                        float v0 = gelu_tanh(acc[mt][nt][hh * 2 + 0] + bb);
                        float v1 = gelu_tanh(acc[mt][nt][hh * 2 + 1] + bb);
                        __half2 h = __floats2half2_rn(v0, v1);
                        asm volatile("st.shared.b32 [%0], %1;"
                                     :: "r"(sH + m * 272 + (wn * 32 + nt * 8 + tt * 2) * 2),
                                        "r"(*(uint32_t*)&h));
                        acc[mt][nt][hh * 2 + 0] = 0.f;
                        acc[mt][nt][hh * 2 + 1] = 0.f;
                    }
                }
        }
    }

    // ---- epilogue: X(gmem) = X(smem-resident) + acc + b2 ----
#pragma unroll
    for (int mt = 0; mt < 4; mt++)
#pragma unroll
        for (int hh = 0; hh < 2; hh++) {
            int m = wm * 64 + mt * 16 + g + hh * 8;
            float bb = b2[m];
            size_t orow = (size_t)m * L;
            uint32_t xrow = sB + (uint32_t)(m >> 5) * B_STAGE_B + (uint32_t)(m & 31) * 272;
#pragma unroll
            for (int nt = 0; nt < 4; nt++) {
                int col = wn * 32 + nt * 8 + tt * 2;
                uint32_t xv;
                asm volatile("ld.shared.b32 %0, [%1];" : "=r"(xv) : "r"(xrow + col * 2));
                float2 rr = __half22float2(*(__half2*)&xv);
                float v0 = acc[mt][nt][hh * 2 + 0] + bb + rr.x;
                float v1 = acc[mt][nt][hh * 2 + 1] + bb + rr.y;
                *(__half2*)&Xb[orow + col] = __floats2half2_rn(v0, v1);
            }
        }
}

// ---------------- LayerNorm over channels: fp16 in, fp32 out ----------------
__global__ __launch_bounds__(256) void ln_kernel(const __half* __restrict__ S,
                                                 const float* __restrict__ g,
                                                 const float* __restrict__ bt,
                                                 float* __restrict__ out) {
    int b = blockIdx.y;
    int l0 = blockIdx.x * 128;
    int tx = threadIdx.x & 63;
    int ty = threadIdx.x >> 6;     // 0..3
    const __half2* Sb = (const __half2*)S;
    uint32_t r[64];
    float s0 = 0.f, s1 = 0.f, q0 = 0.f, q1 = 0.f;
#pragma unroll
    for (int q = 0; q < 64; q++) {
        int c = ty + 4 * q;
        __half2 h = Sb[(size_t)(b * NC + c) * 4096 + (l0 >> 1) + tx];
        r[q] = *(uint32_t*)&h;
        float2 f = __half22float2(h);
        s0 += f.x; s1 += f.y;
        q0 = fmaf(f.x, f.x, q0);
        q1 = fmaf(f.y, f.y, q1);
    }
    __shared__ float2 ssum[4][64], ssq[4][64];
    __shared__ float2 smu[64], srs[64];
    ssum[ty][tx] = make_float2(s0, s1);
    ssq[ty][tx] = make_float2(q0, q1);
    __syncthreads();
    if (ty == 0) {
        float2 s = ssum[0][tx], q = ssq[0][tx];
#pragma unroll
        for (int t = 1; t < 4; t++) {
            s.x += ssum[t][tx].x; s.y += ssum[t][tx].y;
            q.x += ssq[t][tx].x;  q.y += ssq[t][tx].y;
        }
        float mu0 = s.x * (1.f / NC), mu1 = s.y * (1.f / NC);
        float v0 = q.x * (1.f / NC) - mu0 * mu0;
        float v1 = q.y * (1.f / NC) - mu1 * mu1;
        smu[tx] = make_float2(mu0, mu1);
        srs[tx] = make_float2(rsqrtf(v0 + 1e-5f), rsqrtf(v1 + 1e-5f));
    }
    __syncthreads();
    float2 mu = smu[tx], rs = srs[tx];
#pragma unroll
    for (int q = 0; q < 64; q++) {
        int c = ty + 4 * q;
        __half2 h = *(__half2*)&r[q];
        float2 f = __half22float2(h);
        float gg = g[c], bbv = bt[c];
        float o0 = (f.x - mu.x) * rs.x * gg + bbv;
        float o1 = (f.y - mu.y) * rs.y * gg + bbv;
        *(float2*)&out[(size_t)(b * NC + c) * 8192 + l0 + 2 * tx] = make_float2(o0, o1);
    }
}

// ---------------- launch ----------------
static void* sym_addr(const void* sym) {
    void* p = nullptr;
    cudaGetSymbolAddress(&p, sym);
    return p;
}

extern "C" void kernel_launch(void* const* d_in, const int* in_sizes, int n_in,
                              void* d_out, int out_size) {
    const float* x     = (const float*)d_in[0];
    const float* ab_w1 = (const float*)d_in[1];
    const float* ab_b1 = (const float*)d_in[2];
    const float* ab_w2 = (const float*)d_in[3];
    const float* ab_b2 = (const float*)d_in[4];
    const float* db_w1 = (const float*)d_in[5];
    const float* db_b1 = (const float*)d_in[6];
    const float* db_w2 = (const float*)d_in[7];
    const float* db_b2 = (const float*)d_in[8];
    const float* ln_g  = (const float*)d_in[9];
    const float* ln_b  = (const float*)d_in[10];
    float* out = (float*)d_out;

    __half* D1 = (__half*)sym_addr(g_D1);
    __half* D2 = (__half*)sym_addr(g_D2);
    __half* D3 = (__half*)sym_addr(g_D3);
    __half* A3 = (__half*)sym_addr(g_A3);
    __half* S  = (__half*)sym_addr(g_S);
    __half* Wh = (__half*)sym_addr(g_Wh);

    cudaFuncSetAttribute(resblock_all, cudaFuncAttributeMaxDynamicSharedMemorySize, RS_SMEM);
    cudaFuncSetAttribute(fused_dwt,  cudaFuncAttributeMaxDynamicSharedMemorySize, DWT_SMEM_F * 4);
    cudaFuncSetAttribute(fused_idwt, cudaFuncAttributeMaxDynamicSharedMemorySize, IDWT_SMEM_B);

    const int ROWS = NB * NC;   // 4096

    convw_kernel<<<64, 256>>>(ab_w1, ab_w2, db_w1, db_w2, Wh);

    fused_dwt<<<ROWS, 512, DWT_SMEM_F * 4>>>(x, D1, D2, D3, A3);

    resblock_all<<<1024, 512, RS_SMEM>>>(D3, A3, D2, D1, Wh,
                                         ab_b1, ab_b2, db_b1, db_b2);

    fused_idwt<<<ROWS, 512, IDWT_SMEM_B>>>(A3, D3, D2, D1, x, S);

    ln_kernel<<<dim3(8192 / 128, NB), 256>>>(S, ln_g, ln_b, out);
}